// round 1
// baseline (speedup 1.0000x reference)
#include <cuda_runtime.h>
#include <cuda_bf16.h>
#include <math.h>

// Problem constants
#define Lnum 8
#define Bb   8
#define Nn   1024
#define Ww   768
#define Hh   12
#define Cc   64
#define ROWS (Bb*Nn)          // 8192 token rows

// ---------------- scratch (no cudaMalloc allowed) ----------------
__device__ float g_y   [ROWS * Ww];        // LN output          25 MB
__device__ float g_qkv [ROWS * 3 * Ww];    // qkv                75 MB
__device__ float g_attn[ROWS * Ww];        // attention output   25 MB
__device__ float g_fc  [ROWS * 4 * Ww];    // fc+gelu output    100 MB

// ---------------- LayerNorm: one block per row ----------------
__global__ void __launch_bounds__(256) ln_kernel(const float* __restrict__ x,
                                                 const float* __restrict__ g,
                                                 const float* __restrict__ b,
                                                 float* __restrict__ y)
{
    __shared__ float row[Ww];
    __shared__ float red[256];
    const int r   = blockIdx.x;
    const int tid = threadIdx.x;
    const float* xr = x + (size_t)r * Ww;

    float s = 0.f;
    #pragma unroll
    for (int i = tid; i < Ww; i += 256) { float v = xr[i]; row[i] = v; s += v; }
    red[tid] = s; __syncthreads();
    for (int o = 128; o > 0; o >>= 1) { if (tid < o) red[tid] += red[tid + o]; __syncthreads(); }
    const float mean = red[0] * (1.f / Ww);
    __syncthreads();

    float s2 = 0.f;
    #pragma unroll
    for (int i = tid; i < Ww; i += 256) { float d = row[i] - mean; s2 += d * d; }
    red[tid] = s2; __syncthreads();
    for (int o = 128; o > 0; o >>= 1) { if (tid < o) red[tid] += red[tid + o]; __syncthreads(); }
    const float var = red[0] * (1.f / Ww);
    const float w = rsqrtf(var + 1e-5f);

    float* yr = y + (size_t)r * Ww;
    #pragma unroll
    for (int i = tid; i < Ww; i += 256)
        yr[i] = (row[i] - mean) * w * g[i] + b[i];
}

// ---------------- GEMM: C = A[MxK] * B[KxN] + bias (+res) (gelu) ----------------
// 128x128 tile, BK=8, 256 threads, 8x8 per thread (split 4+4 layout)
template<int RES, int GELU>
__global__ void __launch_bounds__(256, 2) gemm_kernel(const float* __restrict__ A,
                                                      const float* __restrict__ B,
                                                      const float* __restrict__ bias,
                                                      const float* __restrict__ Rz,
                                                      float* __restrict__ C,
                                                      int M, int K, int N)
{
    __shared__ float As[8][128];
    __shared__ float Bs[8][128];

    const int tid = threadIdx.x;
    const int tx = tid & 15;
    const int ty = tid >> 4;
    const int n0 = blockIdx.x * 128;
    const int m0 = blockIdx.y * 128;

    float acc[8][8];
    #pragma unroll
    for (int i = 0; i < 8; i++)
        #pragma unroll
        for (int j = 0; j < 8; j++) acc[i][j] = 0.f;

    const int arow = tid >> 1;          // 0..127
    const int acol = (tid & 1) * 4;     // 0 or 4
    const int brow = tid >> 5;          // 0..7
    const int bcol = (tid & 31) * 4;    // 0..124

    const float* Aptr = A + (size_t)(m0 + arow) * K + acol;
    const float* Bptr = B + (size_t)brow * N + n0 + bcol;

    for (int k0 = 0; k0 < K; k0 += 8) {
        const float4 av = *(const float4*)(Aptr + k0);
        const float4 bv = *(const float4*)(Bptr + (size_t)k0 * N);
        __syncthreads();
        As[acol + 0][arow] = av.x;
        As[acol + 1][arow] = av.y;
        As[acol + 2][arow] = av.z;
        As[acol + 3][arow] = av.w;
        *(float4*)&Bs[brow][bcol] = bv;
        __syncthreads();

        #pragma unroll
        for (int kk = 0; kk < 8; kk++) {
            const float4 a0 = *(const float4*)&As[kk][ty * 4];
            const float4 a1 = *(const float4*)&As[kk][64 + ty * 4];
            const float4 b0 = *(const float4*)&Bs[kk][tx * 4];
            const float4 b1 = *(const float4*)&Bs[kk][64 + tx * 4];
            const float ar[8] = {a0.x, a0.y, a0.z, a0.w, a1.x, a1.y, a1.z, a1.w};
            const float br[8] = {b0.x, b0.y, b0.z, b0.w, b1.x, b1.y, b1.z, b1.w};
            #pragma unroll
            for (int i = 0; i < 8; i++)
                #pragma unroll
                for (int j = 0; j < 8; j++)
                    acc[i][j] = fmaf(ar[i], br[j], acc[i][j]);
        }
    }

    // epilogue
    #pragma unroll
    for (int i = 0; i < 8; i++) {
        const int rloc = (i < 4) ? (ty * 4 + i) : (64 + ty * 4 + i - 4);
        const size_t rowoff = (size_t)(m0 + rloc) * N;
        #pragma unroll
        for (int jb = 0; jb < 2; jb++) {
            const int cloc = (jb == 0) ? (tx * 4) : (64 + tx * 4);
            const int col = n0 + cloc;
            float v[4];
            #pragma unroll
            for (int j = 0; j < 4; j++) {
                float t = acc[i][jb * 4 + j] + bias[col + j];
                if (GELU) t = 0.5f * t * (1.0f + erff(t * 0.70710678118654752f));
                v[j] = t;
            }
            if (RES) {
                const float4 rv = *(const float4*)(Rz + rowoff + col);
                v[0] += rv.x; v[1] += rv.y; v[2] += rv.z; v[3] += rv.w;
            }
            float4 ov; ov.x = v[0]; ov.y = v[1]; ov.z = v[2]; ov.w = v[3];
            *(float4*)(C + rowoff + col) = ov;
        }
    }
}

// ---------------- fused attention (flash-style), fp32 ----------------
// grid: bh * 128 + rowblock; 8 warps/block, 1 query row per warp
__global__ void __launch_bounds__(256) attn_kernel(const float* __restrict__ qkv,
                                                   float* __restrict__ out)
{
    __shared__ float Kt[64][65];   // K transposed [c][key]
    __shared__ float Vs[64][64];   // V [key][c]
    __shared__ float qs[8][64];
    __shared__ float sc[8][64];

    const int tid  = threadIdx.x;
    const int warp = tid >> 5;
    const int lane = tid & 31;
    const int blk  = blockIdx.x;
    const int bh   = blk >> 7;      // / 128
    const int rb   = blk & 127;
    const int b    = bh / Hh;
    const int h    = bh % Hh;
    const int qrow = rb * 8 + warp;

    const float* base = qkv + (size_t)(b * Nn) * (3 * Ww) + h * (3 * Cc);

    // load this warp's q row into smem
    const float* qrp = base + (size_t)qrow * (3 * Ww);
    qs[warp][lane]      = qrp[lane];
    qs[warp][lane + 32] = qrp[lane + 32];
    __syncwarp();

    float m_run = -1e30f, lpart = 0.f, O0 = 0.f, O1 = 0.f;

    for (int kt = 0; kt < 16; kt++) {
        __syncthreads();   // previous tile compute done
        // cooperative load of K(transposed) and V tile
        #pragma unroll
        for (int p = 0; p < 4; p++) {
            const int flat = (p * 256 + tid) * 4;
            const int key = flat >> 6;
            const int c   = flat & 63;
            const float* kr = base + (size_t)(kt * 64 + key) * (3 * Ww) + 64 + c;
            const float4 k4 = *(const float4*)kr;
            Kt[c + 0][key] = k4.x;
            Kt[c + 1][key] = k4.y;
            Kt[c + 2][key] = k4.z;
            Kt[c + 3][key] = k4.w;
            const float* vr = base + (size_t)(kt * 64 + key) * (3 * Ww) + 128 + c;
            *(float4*)&Vs[key][c] = *(const float4*)vr;
        }
        __syncthreads();

        // scores: this lane handles keys lane and lane+32
        float s0 = 0.f, s1 = 0.f;
        #pragma unroll
        for (int c = 0; c < 64; c++) {
            const float qc = qs[warp][c];
            s0 = fmaf(qc, Kt[c][lane],      s0);
            s1 = fmaf(qc, Kt[c][lane + 32], s1);
        }
        s0 *= 0.125f;   // scale^2 = 1/sqrt(C) = 1/8
        s1 *= 0.125f;

        float mt = fmaxf(s0, s1);
        #pragma unroll
        for (int o = 16; o > 0; o >>= 1)
            mt = fmaxf(mt, __shfl_xor_sync(0xffffffffu, mt, o));

        const float m_new = fmaxf(m_run, mt);
        const float alpha = __expf(m_run - m_new);
        const float p0 = __expf(s0 - m_new);
        const float p1 = __expf(s1 - m_new);
        lpart = lpart * alpha + p0 + p1;
        O0 *= alpha; O1 *= alpha;
        sc[warp][lane]      = p0;
        sc[warp][lane + 32] = p1;
        __syncwarp();

        #pragma unroll
        for (int s = 0; s < 64; s++) {
            const float p = sc[warp][s];
            O0 = fmaf(p, Vs[s][lane],      O0);
            O1 = fmaf(p, Vs[s][lane + 32], O1);
        }
        m_run = m_new;
    }

    float lt = lpart;
    #pragma unroll
    for (int o = 16; o > 0; o >>= 1)
        lt += __shfl_xor_sync(0xffffffffu, lt, o);
    const float inv = 1.f / lt;

    float* orow = out + (size_t)(b * Nn + qrow) * Ww + h * Cc;
    orow[lane]      = O0 * inv;
    orow[lane + 32] = O1 * inv;
}

// ---------------- launcher ----------------
extern "C" void kernel_launch(void* const* d_in, const int* in_sizes, int n_in,
                              void* d_out, int out_size)
{
    const float* x    = (const float*)d_in[0];
    const float* Wqkv = (const float*)d_in[1];
    const float* bqkv = (const float*)d_in[2];
    const float* Wo   = (const float*)d_in[3];
    const float* bo   = (const float*)d_in[4];
    const float* Wfc  = (const float*)d_in[5];
    const float* bfc  = (const float*)d_in[6];
    const float* Wpr  = (const float*)d_in[7];
    const float* bpr  = (const float*)d_in[8];
    const float* g1   = (const float*)d_in[9];
    const float* b1   = (const float*)d_in[10];
    const float* g2   = (const float*)d_in[11];
    const float* b2   = (const float*)d_in[12];

    float* h = (float*)d_out;   // hidden state lives in the output buffer

    float *py, *pqkv, *pattn, *pfc;
    cudaGetSymbolAddress((void**)&py,    g_y);
    cudaGetSymbolAddress((void**)&pqkv,  g_qkv);
    cudaGetSymbolAddress((void**)&pattn, g_attn);
    cudaGetSymbolAddress((void**)&pfc,   g_fc);

    cudaMemcpyAsync(h, x, (size_t)ROWS * Ww * sizeof(float), cudaMemcpyDeviceToDevice);

    for (int l = 0; l < Lnum; l++) {
        const float* wqkv = Wqkv + (size_t)l * Ww * 3 * Ww;
        const float* bq   = bqkv + (size_t)l * 3 * Ww;
        const float* wo   = Wo   + (size_t)l * Ww * Ww;
        const float* bo_  = bo   + (size_t)l * Ww;
        const float* wfc  = Wfc  + (size_t)l * Ww * 4 * Ww;
        const float* bf   = bfc  + (size_t)l * 4 * Ww;
        const float* wpr  = Wpr  + (size_t)l * 4 * Ww * Ww;
        const float* bp   = bpr  + (size_t)l * Ww;

        // LN1
        ln_kernel<<<ROWS, 256>>>(h, g1 + l * Ww, b1 + l * Ww, py);
        // qkv = y @ Wqkv + bqkv
        gemm_kernel<0,0><<<dim3(3 * Ww / 128, ROWS / 128), 256>>>(
            py, wqkv, bq, nullptr, pqkv, ROWS, Ww, 3 * Ww);
        // attention
        attn_kernel<<<Bb * Hh * (Nn / 8), 256>>>(pqkv, pattn);
        // h = h + attn @ Wo + bo
        gemm_kernel<1,0><<<dim3(Ww / 128, ROWS / 128), 256>>>(
            pattn, wo, bo_, h, h, ROWS, Ww, Ww);
        // LN2
        ln_kernel<<<ROWS, 256>>>(h, g2 + l * Ww, b2 + l * Ww, py);
        // fc = gelu(y @ Wfc + bfc)
        gemm_kernel<0,1><<<dim3(4 * Ww / 128, ROWS / 128), 256>>>(
            py, wfc, bf, nullptr, pfc, ROWS, Ww, 4 * Ww);
        // h = h + fc @ Wpr + bpr
        gemm_kernel<1,0><<<dim3(Ww / 128, ROWS / 128), 256>>>(
            pfc, wpr, bp, h, h, ROWS, 4 * Ww, Ww);
    }
}

// round 3
// speedup vs baseline: 1.9423x; 1.9423x over previous
#include <cuda_runtime.h>
#include <cuda_bf16.h>
#include <math.h>
#include <stdint.h>

// Problem constants
#define Lnum 8
#define Bb   8
#define Nn   1024
#define Ww   768
#define Hh   12
#define Cc   64
#define ROWS (Bb*Nn)          // 8192 token rows

// ---------------- scratch (no cudaMalloc allowed) ----------------
__device__ float g_y   [ROWS * Ww];
__device__ float g_qkv [ROWS * 3 * Ww];
__device__ float g_attn[ROWS * Ww];
__device__ float g_fc  [ROWS * 4 * Ww];

// =================== portable PTX helpers ===================
__device__ __forceinline__ uint32_t smem_to_u32(const void* smem_ptr) {
    uint32_t addr;
    asm("{ .reg .u64 tmp; cvta.to.shared.u64 tmp, %1; cvt.u32.u64 %0, tmp; }"
        : "=r"(addr) : "l"(smem_ptr));
    return addr;
}

__device__ __forceinline__ void ldsm_x4(uint32_t* r, uint32_t addr) {
    asm volatile("ldmatrix.sync.aligned.m8n8.x4.shared.b16 {%0,%1,%2,%3}, [%4];"
        : "=r"(r[0]), "=r"(r[1]), "=r"(r[2]), "=r"(r[3]) : "r"(addr));
}
__device__ __forceinline__ void ldsm_x2_t(uint32_t* r, uint32_t addr) {
    asm volatile("ldmatrix.sync.aligned.m8n8.x2.trans.shared.b16 {%0,%1}, [%2];"
        : "=r"(r[0]), "=r"(r[1]) : "r"(addr));
}
__device__ __forceinline__ void mma16816(float* d, const uint32_t* a, const uint32_t* b) {
    asm volatile(
        "mma.sync.aligned.m16n8k16.row.col.f32.bf16.bf16.f32 "
        "{%0,%1,%2,%3}, {%4,%5,%6,%7}, {%8,%9}, {%0,%1,%2,%3};\n"
        : "+f"(d[0]), "+f"(d[1]), "+f"(d[2]), "+f"(d[3])
        : "r"(a[0]), "r"(a[1]), "r"(a[2]), "r"(a[3]), "r"(b[0]), "r"(b[1]));
}

__device__ __forceinline__ uint32_t bfpack(__nv_bfloat16 a, __nv_bfloat16 b) {
    uint16_t ua = *(uint16_t*)&a, ub = *(uint16_t*)&b;
    return (uint32_t)ua | ((uint32_t)ub << 16);
}

// ---------------- LayerNorm: one block per row ----------------
__global__ void __launch_bounds__(256) ln_kernel(const float* __restrict__ x,
                                                 const float* __restrict__ g,
                                                 const float* __restrict__ b,
                                                 float* __restrict__ y)
{
    __shared__ float row[Ww];
    __shared__ float red[256];
    const int r   = blockIdx.x;
    const int tid = threadIdx.x;
    const float* xr = x + (size_t)r * Ww;

    float s = 0.f;
    #pragma unroll
    for (int i = tid; i < Ww; i += 256) { float v = xr[i]; row[i] = v; s += v; }
    red[tid] = s; __syncthreads();
    for (int o = 128; o > 0; o >>= 1) { if (tid < o) red[tid] += red[tid + o]; __syncthreads(); }
    const float mean = red[0] * (1.f / Ww);
    __syncthreads();

    float s2 = 0.f;
    #pragma unroll
    for (int i = tid; i < Ww; i += 256) { float d = row[i] - mean; s2 += d * d; }
    red[tid] = s2; __syncthreads();
    for (int o = 128; o > 0; o >>= 1) { if (tid < o) red[tid] += red[tid + o]; __syncthreads(); }
    const float var = red[0] * (1.f / Ww);
    const float w = rsqrtf(var + 1e-5f);

    float* yr = y + (size_t)r * Ww;
    #pragma unroll
    for (int i = tid; i < Ww; i += 256)
        yr[i] = (row[i] - mean) * w * g[i] + b[i];
}

// =================== bf16x3 tensor-core GEMM (mma.sync) ===================
// C[M,N] = A[M,K]@B[K,N] + bias (+res)(gelu), fp32 in/out.
// Tile 128x128, BK=32, 256 threads (8 warps: 2m x 4n), warp does 64x32.
// SMEM per buffer: Ahi[128][40] Alo[128][40] bf16 ; Bhi[32][136] Blo[32][136] bf16
#define A_STRIDE 40
#define B_STRIDE 136
#define A_BYTES (128 * A_STRIDE * 2)           // 10240
#define B_BYTES (32 * B_STRIDE * 2)            // 8704
#define BUF_BYTES (2*A_BYTES + 2*B_BYTES)      // 37888
#define OFF_ALO A_BYTES
#define OFF_BHI (2*A_BYTES)
#define OFF_BLO (2*A_BYTES + B_BYTES)
#define GEMM_SMEM (2 * BUF_BYTES)              // 75776

template<int RES, int GELU>
__global__ void __launch_bounds__(256) gemm_tc(const float* __restrict__ A,
                                               const float* __restrict__ B,
                                               const float* __restrict__ bias,
                                               const float* __restrict__ Rz,
                                               float* __restrict__ C,
                                               int M, int K, int N)
{
    extern __shared__ char sm[];
    const uint32_t smem_base = smem_to_u32(sm);
    const int tid  = threadIdx.x;
    const int wid  = tid >> 5;
    const int lane = tid & 31;
    const int wm   = wid >> 2;       // 0..1
    const int wn   = wid & 3;        // 0..3
    const int n0 = blockIdx.x * 128;
    const int m0 = blockIdx.y * 128;

    float acc[4][4][4];
    #pragma unroll
    for (int i = 0; i < 4; i++)
        #pragma unroll
        for (int j = 0; j < 4; j++)
            #pragma unroll
            for (int q = 0; q < 4; q++) acc[i][j][q] = 0.f;

    const int NC = K / 32;

    // gmem load indices: A: 4 float4/thread; B: 4 float4/thread
    const int af4 = tid * 4;                 // a: f4 id base
    const int arow = af4 >> 3;               // row (2 threads per 32-col row? no: 8 f4/row)
    // careful: f4 ids tid*4..tid*4+3 all share row = (tid*4)/8 = tid/2 and c4 = (tid&1)*4 + p
    const int a_r = tid >> 1;
    const int a_c4 = (tid & 1) * 4;
    const int b_r = tid >> 3;
    const int b_c4 = (tid & 7) * 4;
    (void)af4; (void)arow;

    float4 ra[4], rb[4];

    auto load_chunk = [&](int kc) {
        const float* ap = A + (size_t)(m0 + a_r) * K + kc * 32 + a_c4 * 4;
        #pragma unroll
        for (int p = 0; p < 4; p++) ra[p] = *(const float4*)(ap + p * 4);
        const float* bp = B + (size_t)(kc * 32 + b_r) * N + n0 + b_c4 * 4;
        #pragma unroll
        for (int p = 0; p < 4; p++) rb[p] = *(const float4*)(bp + p * 4);
    };

    auto store_chunk = [&](int bsel) {
        char* buf = sm + bsel * BUF_BYTES;
        #pragma unroll
        for (int p = 0; p < 4; p++) {
            const float f[4] = {ra[p].x, ra[p].y, ra[p].z, ra[p].w};
            uint32_t hw[2], lw[2];
            #pragma unroll
            for (int i = 0; i < 2; i++) {
                __nv_bfloat16 h0 = __float2bfloat16(f[2*i]);
                __nv_bfloat16 h1 = __float2bfloat16(f[2*i+1]);
                __nv_bfloat16 l0 = __float2bfloat16(f[2*i]   - __bfloat162float(h0));
                __nv_bfloat16 l1 = __float2bfloat16(f[2*i+1] - __bfloat162float(h1));
                hw[i] = bfpack(h0, h1); lw[i] = bfpack(l0, l1);
            }
            const uint32_t off = (uint32_t)a_r * (A_STRIDE*2) + (a_c4 + p) * 8;
            *(uint2*)(buf + off)           = make_uint2(hw[0], hw[1]);
            *(uint2*)(buf + OFF_ALO + off) = make_uint2(lw[0], lw[1]);
        }
        #pragma unroll
        for (int p = 0; p < 4; p++) {
            const float f[4] = {rb[p].x, rb[p].y, rb[p].z, rb[p].w};
            uint32_t hw[2], lw[2];
            #pragma unroll
            for (int i = 0; i < 2; i++) {
                __nv_bfloat16 h0 = __float2bfloat16(f[2*i]);
                __nv_bfloat16 h1 = __float2bfloat16(f[2*i+1]);
                __nv_bfloat16 l0 = __float2bfloat16(f[2*i]   - __bfloat162float(h0));
                __nv_bfloat16 l1 = __float2bfloat16(f[2*i+1] - __bfloat162float(h1));
                hw[i] = bfpack(h0, h1); lw[i] = bfpack(l0, l1);
            }
            const uint32_t off = (uint32_t)b_r * (B_STRIDE*2) + (b_c4 + p) * 8;
            *(uint2*)(buf + OFF_BHI + off) = make_uint2(hw[0], hw[1]);
            *(uint2*)(buf + OFF_BLO + off) = make_uint2(lw[0], lw[1]);
        }
    };

    // per-lane ldmatrix base offsets
    const uint32_t a_lrow = (uint32_t)(wm * 64 + (lane & 15));    // row within tile
    const uint32_t a_koff = (uint32_t)(8 * (lane >> 4));          // k offset 0/8
    const uint32_t b_lrow = (uint32_t)(lane & 15);                // k row
    const uint32_t b_noff = (uint32_t)(wn * 32);

    load_chunk(0);
    store_chunk(0);
    __syncthreads();

    for (int ic = 0; ic < NC; ic++) {
        const int bsel = ic & 1;
        if (ic + 1 < NC) load_chunk(ic + 1);

        const uint32_t buf = smem_base + bsel * BUF_BYTES;
        #pragma unroll
        for (int k16 = 0; k16 < 2; k16++) {
            uint32_t ah[4][4], al[4][4], bh[4][2], bl[4][2];
            #pragma unroll
            for (int mi = 0; mi < 4; mi++) {
                const uint32_t aoff = (a_lrow + mi * 16) * (A_STRIDE*2)
                                    + (k16 * 16 + a_koff) * 2;
                ldsm_x4(ah[mi], buf + aoff);
                ldsm_x4(al[mi], buf + OFF_ALO + aoff);
            }
            #pragma unroll
            for (int ni = 0; ni < 4; ni++) {
                const uint32_t boff = (k16 * 16 + b_lrow) * (B_STRIDE*2)
                                    + (b_noff + ni * 8) * 2;
                ldsm_x2_t(bh[ni], buf + OFF_BHI + boff);
                ldsm_x2_t(bl[ni], buf + OFF_BLO + boff);
            }
            #pragma unroll
            for (int mi = 0; mi < 4; mi++)
                #pragma unroll
                for (int ni = 0; ni < 4; ni++) {
                    mma16816(acc[mi][ni], ah[mi], bh[ni]);
                    mma16816(acc[mi][ni], ah[mi], bl[ni]);
                    mma16816(acc[mi][ni], al[mi], bh[ni]);
                }
        }

        if (ic + 1 < NC) store_chunk((ic + 1) & 1);
        __syncthreads();
    }

    // ---- epilogue ----
    const int g = lane >> 2;
    const int t = lane & 3;
    #pragma unroll
    for (int mi = 0; mi < 4; mi++) {
        #pragma unroll
        for (int half = 0; half < 2; half++) {
            const int m_ = m0 + wm * 64 + mi * 16 + g + half * 8;
            float* crow = C + (size_t)m_ * N;
            const float* rrow = RES ? (Rz + (size_t)m_ * N) : nullptr;
            #pragma unroll
            for (int ni = 0; ni < 4; ni++) {
                const int n_ = n0 + wn * 32 + ni * 8 + 2 * t;
                float v0 = acc[mi][ni][half * 2 + 0] + bias[n_];
                float v1 = acc[mi][ni][half * 2 + 1] + bias[n_ + 1];
                if (GELU) {
                    v0 = 0.5f * v0 * (1.0f + erff(v0 * 0.70710678118654752f));
                    v1 = 0.5f * v1 * (1.0f + erff(v1 * 0.70710678118654752f));
                }
                if (RES) {
                    const float2 rv = *(const float2*)(rrow + n_);
                    v0 += rv.x; v1 += rv.y;
                }
                *(float2*)(crow + n_) = make_float2(v0, v1);
            }
        }
    }
}

// ---------------- fused attention: 4 query rows per warp ----------------
#define ATTN_SMEM ((64*65 + 64*64 + 32*64 + 32*64) * 4)
__global__ void __launch_bounds__(256) attn_kernel(const float* __restrict__ qkv,
                                                   float* __restrict__ out)
{
    extern __shared__ float smf[];
    float (*Kt)[65] = (float(*)[65])smf;                          // [64][65]
    float (*Vs)[64] = (float(*)[64])(smf + 64*65);                // [64][64]
    float (*qs)[64] = (float(*)[64])(smf + 64*65 + 64*64);        // [32][64]
    float (*sc)[64] = (float(*)[64])(smf + 64*65 + 64*64 + 32*64);// [32][64]

    const int tid  = threadIdx.x;
    const int warp = tid >> 5;
    const int lane = tid & 31;
    const int blk  = blockIdx.x;
    const int bh   = blk >> 5;
    const int rb   = blk & 31;
    const int b    = bh / Hh;
    const int h    = bh % Hh;

    const float* base = qkv + (size_t)(b * Nn) * (3 * Ww) + h * (3 * Cc);

    for (int i = tid; i < 32 * 64; i += 256) {
        const int j = i >> 6, c = i & 63;
        qs[j][c] = base[(size_t)(rb * 32 + j) * (3 * Ww) + c];
    }

    const int r0 = warp * 4;
    float m_run[4], lsum[4], O0[4], O1[4];
    #pragma unroll
    for (int r = 0; r < 4; r++) { m_run[r] = -1e30f; lsum[r] = 0.f; O0[r] = 0.f; O1[r] = 0.f; }

    for (int kt = 0; kt < 16; kt++) {
        __syncthreads();
        #pragma unroll
        for (int p = 0; p < 4; p++) {
            const int flat = (p * 256 + tid) * 4;
            const int key = flat >> 6;
            const int c   = flat & 63;
            const float* kr = base + (size_t)(kt * 64 + key) * (3 * Ww) + 64 + c;
            const float4 k4 = *(const float4*)kr;
            Kt[c + 0][key] = k4.x;
            Kt[c + 1][key] = k4.y;
            Kt[c + 2][key] = k4.z;
            Kt[c + 3][key] = k4.w;
            const float* vr = base + (size_t)(kt * 64 + key) * (3 * Ww) + 128 + c;
            *(float4*)&Vs[key][c] = *(const float4*)vr;
        }
        __syncthreads();

        float s0[4] = {0, 0, 0, 0}, s1[4] = {0, 0, 0, 0};
        #pragma unroll 4
        for (int c = 0; c < 64; c++) {
            const float k0 = Kt[c][lane];
            const float k1 = Kt[c][lane + 32];
            #pragma unroll
            for (int r = 0; r < 4; r++) {
                const float qc = qs[r0 + r][c];
                s0[r] = fmaf(qc, k0, s0[r]);
                s1[r] = fmaf(qc, k1, s1[r]);
            }
        }
        #pragma unroll
        for (int r = 0; r < 4; r++) {
            const float a = s0[r] * 0.125f;
            const float bq = s1[r] * 0.125f;
            float mt = fmaxf(a, bq);
            #pragma unroll
            for (int o = 16; o > 0; o >>= 1)
                mt = fmaxf(mt, __shfl_xor_sync(0xffffffffu, mt, o));
            const float mn = fmaxf(m_run[r], mt);
            const float alpha = __expf(m_run[r] - mn);
            const float p0 = __expf(a - mn);
            const float p1 = __expf(bq - mn);
            lsum[r] = lsum[r] * alpha + p0 + p1;
            O0[r] *= alpha; O1[r] *= alpha;
            sc[r0 + r][lane]      = p0;
            sc[r0 + r][lane + 32] = p1;
            m_run[r] = mn;
        }
        __syncwarp();
        #pragma unroll 4
        for (int s_ = 0; s_ < 64; s_++) {
            const float v0 = Vs[s_][lane];
            const float v1 = Vs[s_][lane + 32];
            #pragma unroll
            for (int r = 0; r < 4; r++) {
                const float p = sc[r0 + r][s_];
                O0[r] = fmaf(p, v0, O0[r]);
                O1[r] = fmaf(p, v1, O1[r]);
            }
        }
    }

    #pragma unroll
    for (int r = 0; r < 4; r++) {
        float lt = lsum[r];
        #pragma unroll
        for (int o = 16; o > 0; o >>= 1)
            lt += __shfl_xor_sync(0xffffffffu, lt, o);
        const float inv = 1.f / lt;
        float* orow = out + (size_t)(b * Nn + rb * 32 + r0 + r) * Ww + h * Cc;
        orow[lane]      = O0[r] * inv;
        orow[lane + 32] = O1[r] * inv;
    }
}

// ---------------- launcher ----------------
extern "C" void kernel_launch(void* const* d_in, const int* in_sizes, int n_in,
                              void* d_out, int out_size)
{
    const float* x    = (const float*)d_in[0];
    const float* Wqkv = (const float*)d_in[1];
    const float* bqkv = (const float*)d_in[2];
    const float* Wo   = (const float*)d_in[3];
    const float* bo   = (const float*)d_in[4];
    const float* Wfc  = (const float*)d_in[5];
    const float* bfc  = (const float*)d_in[6];
    const float* Wpr  = (const float*)d_in[7];
    const float* bpr  = (const float*)d_in[8];
    const float* g1   = (const float*)d_in[9];
    const float* b1   = (const float*)d_in[10];
    const float* g2   = (const float*)d_in[11];
    const float* b2   = (const float*)d_in[12];

    float* h = (float*)d_out;

    float *py, *pqkv, *pattn, *pfc;
    cudaGetSymbolAddress((void**)&py,    g_y);
    cudaGetSymbolAddress((void**)&pqkv,  g_qkv);
    cudaGetSymbolAddress((void**)&pattn, g_attn);
    cudaGetSymbolAddress((void**)&pfc,   g_fc);

    cudaFuncSetAttribute(gemm_tc<0,0>, cudaFuncAttributeMaxDynamicSharedMemorySize, GEMM_SMEM);
    cudaFuncSetAttribute(gemm_tc<1,0>, cudaFuncAttributeMaxDynamicSharedMemorySize, GEMM_SMEM);
    cudaFuncSetAttribute(gemm_tc<0,1>, cudaFuncAttributeMaxDynamicSharedMemorySize, GEMM_SMEM);
    cudaFuncSetAttribute(attn_kernel,  cudaFuncAttributeMaxDynamicSharedMemorySize, ATTN_SMEM);

    cudaMemcpyAsync(h, x, (size_t)ROWS * Ww * sizeof(float), cudaMemcpyDeviceToDevice);

    for (int l = 0; l < Lnum; l++) {
        const float* wqkv = Wqkv + (size_t)l * Ww * 3 * Ww;
        const float* bq   = bqkv + (size_t)l * 3 * Ww;
        const float* wo   = Wo   + (size_t)l * Ww * Ww;
        const float* bo_  = bo   + (size_t)l * Ww;
        const float* wfc  = Wfc  + (size_t)l * Ww * 4 * Ww;
        const float* bf   = bfc  + (size_t)l * 4 * Ww;
        const float* wpr  = Wpr  + (size_t)l * 4 * Ww * Ww;
        const float* bp   = bpr  + (size_t)l * Ww;

        ln_kernel<<<ROWS, 256>>>(h, g1 + l * Ww, b1 + l * Ww, py);
        gemm_tc<0,0><<<dim3(3 * Ww / 128, ROWS / 128), 256, GEMM_SMEM>>>(
            py, wqkv, bq, nullptr, pqkv, ROWS, Ww, 3 * Ww);
        attn_kernel<<<Bb * Hh * (Nn / 32), 256, ATTN_SMEM>>>(pqkv, pattn);
        gemm_tc<1,0><<<dim3(Ww / 128, ROWS / 128), 256, GEMM_SMEM>>>(
            pattn, wo, bo_, h, h, ROWS, Ww, Ww);
        ln_kernel<<<ROWS, 256>>>(h, g2 + l * Ww, b2 + l * Ww, py);
        gemm_tc<0,1><<<dim3(4 * Ww / 128, ROWS / 128), 256, GEMM_SMEM>>>(
            py, wfc, bf, nullptr, pfc, ROWS, Ww, 4 * Ww);
        gemm_tc<1,0><<<dim3(Ww / 128, ROWS / 128), 256, GEMM_SMEM>>>(
            pfc, wpr, bp, h, h, ROWS, 4 * Ww, Ww);
    }
}

// round 4
// speedup vs baseline: 2.3852x; 1.2280x over previous
#include <cuda_runtime.h>
#include <cuda_bf16.h>
#include <math.h>
#include <stdint.h>

// Problem constants
#define Lnum 8
#define Bb   8
#define Nn   1024
#define Ww   768
#define Hh   12
#define Cc   64
#define ROWS (Bb*Nn)          // 8192 token rows

// ---------------- scratch (no cudaMalloc allowed) ----------------
__device__ float g_qkv [ROWS * 3 * Ww];                 // fp32 qkv
__device__ __nv_bfloat16 g_yhi[ROWS * Ww],  g_ylo[ROWS * Ww];    // LN out
__device__ __nv_bfloat16 g_ahi[ROWS * Ww],  g_alo[ROWS * Ww];    // attn out
__device__ __nv_bfloat16 g_fchi[ROWS * 4 * Ww], g_fclo[ROWS * 4 * Ww];
// weights hi/lo (all layers)
__device__ __nv_bfloat16 g_wqkv_hi[Lnum * Ww * 3 * Ww], g_wqkv_lo[Lnum * Ww * 3 * Ww];
__device__ __nv_bfloat16 g_wo_hi  [Lnum * Ww * Ww],     g_wo_lo  [Lnum * Ww * Ww];
__device__ __nv_bfloat16 g_wfc_hi [Lnum * Ww * 4 * Ww], g_wfc_lo [Lnum * Ww * 4 * Ww];
__device__ __nv_bfloat16 g_wpr_hi [Lnum * 4 * Ww * Ww], g_wpr_lo [Lnum * 4 * Ww * Ww];

// =================== portable PTX helpers ===================
__device__ __forceinline__ uint32_t smem_to_u32(const void* smem_ptr) {
    uint32_t addr;
    asm("{ .reg .u64 tmp; cvta.to.shared.u64 tmp, %1; cvt.u32.u64 %0, tmp; }"
        : "=r"(addr) : "l"(smem_ptr));
    return addr;
}
__device__ __forceinline__ void ldsm_x4(uint32_t* r, uint32_t addr) {
    asm volatile("ldmatrix.sync.aligned.m8n8.x4.shared.b16 {%0,%1,%2,%3}, [%4];"
        : "=r"(r[0]), "=r"(r[1]), "=r"(r[2]), "=r"(r[3]) : "r"(addr));
}
__device__ __forceinline__ void ldsm_x2_t(uint32_t* r, uint32_t addr) {
    asm volatile("ldmatrix.sync.aligned.m8n8.x2.trans.shared.b16 {%0,%1}, [%2];"
        : "=r"(r[0]), "=r"(r[1]) : "r"(addr));
}
__device__ __forceinline__ void mma16816(float* d, const uint32_t* a, const uint32_t* b) {
    asm volatile(
        "mma.sync.aligned.m16n8k16.row.col.f32.bf16.bf16.f32 "
        "{%0,%1,%2,%3}, {%4,%5,%6,%7}, {%8,%9}, {%0,%1,%2,%3};\n"
        : "+f"(d[0]), "+f"(d[1]), "+f"(d[2]), "+f"(d[3])
        : "r"(a[0]), "r"(a[1]), "r"(a[2]), "r"(a[3]), "r"(b[0]), "r"(b[1]));
}
__device__ __forceinline__ uint32_t bfpack(__nv_bfloat16 a, __nv_bfloat16 b) {
    uint16_t ua = *(uint16_t*)&a, ub = *(uint16_t*)&b;
    return (uint32_t)ua | ((uint32_t)ub << 16);
}
__device__ __forceinline__ void split2(float x, __nv_bfloat16& h, __nv_bfloat16& l) {
    h = __float2bfloat16(x);
    l = __float2bfloat16(x - __bfloat162float(h));
}

// ---------------- weight conversion: fp32 -> bf16 hi/lo ----------------
__global__ void __launch_bounds__(256) cvt_kernel(const float4* __restrict__ src,
                                                  uint2* __restrict__ hi,
                                                  uint2* __restrict__ lo,
                                                  int n4)
{
    int i = blockIdx.x * 256 + threadIdx.x;
    if (i >= n4) return;
    const float4 x = src[i];
    __nv_bfloat16 h0, h1, h2, h3, l0, l1, l2, l3;
    split2(x.x, h0, l0); split2(x.y, h1, l1);
    split2(x.z, h2, l2); split2(x.w, h3, l3);
    hi[i] = make_uint2(bfpack(h0, h1), bfpack(h2, h3));
    lo[i] = make_uint2(bfpack(l0, l1), bfpack(l2, l3));
}

// ---------------- LayerNorm: one block per row, writes bf16 hi/lo ----------------
__global__ void __launch_bounds__(256) ln_kernel(const float* __restrict__ x,
                                                 const float* __restrict__ g,
                                                 const float* __restrict__ b,
                                                 __nv_bfloat16* __restrict__ yhi,
                                                 __nv_bfloat16* __restrict__ ylo)
{
    __shared__ float row[Ww];
    __shared__ float red[256];
    const int r   = blockIdx.x;
    const int tid = threadIdx.x;
    const float* xr = x + (size_t)r * Ww;

    float s = 0.f;
    #pragma unroll
    for (int i = tid; i < Ww; i += 256) { float v = xr[i]; row[i] = v; s += v; }
    red[tid] = s; __syncthreads();
    for (int o = 128; o > 0; o >>= 1) { if (tid < o) red[tid] += red[tid + o]; __syncthreads(); }
    const float mean = red[0] * (1.f / Ww);
    __syncthreads();

    float s2 = 0.f;
    #pragma unroll
    for (int i = tid; i < Ww; i += 256) { float d = row[i] - mean; s2 += d * d; }
    red[tid] = s2; __syncthreads();
    for (int o = 128; o > 0; o >>= 1) { if (tid < o) red[tid] += red[tid + o]; __syncthreads(); }
    const float var = red[0] * (1.f / Ww);
    const float w = rsqrtf(var + 1e-5f);

    #pragma unroll
    for (int i = tid; i < Ww; i += 256) {
        const float v = (row[i] - mean) * w * g[i] + b[i];
        __nv_bfloat16 h, l; split2(v, h, l);
        yhi[(size_t)r * Ww + i] = h;
        ylo[(size_t)r * Ww + i] = l;
    }
}

// =================== bf16x3 tensor-core GEMM (mma.sync), preconverted operands ===========
// Tile 128x128, BK=32, 256 threads (2m x 4n warps), warp 64x32.
#define A_STRB 80      // bytes per A smem row (32 bf16 + 8 pad)
#define B_STRB 272     // bytes per B smem row (128 bf16 + 8 pad)
#define A_BYTES (128 * A_STRB)                 // 10240
#define B_BYTES (32 * B_STRB)                  // 8704
#define OFF_ALO A_BYTES
#define OFF_BHI (2*A_BYTES)
#define OFF_BLO (2*A_BYTES + B_BYTES)
#define BUF_BYTES (2*A_BYTES + 2*B_BYTES)      // 37888
#define GEMM_SMEM (2 * BUF_BYTES)              // 75776

template<int RES, int GELU, int OUTBF>
__global__ void __launch_bounds__(256) gemm_tc(const __nv_bfloat16* __restrict__ Ahi,
                                               const __nv_bfloat16* __restrict__ Alo,
                                               const __nv_bfloat16* __restrict__ Bhi,
                                               const __nv_bfloat16* __restrict__ Blo,
                                               const float* __restrict__ bias,
                                               const float* __restrict__ Rz,
                                               float* __restrict__ C,
                                               __nv_bfloat16* __restrict__ Chi,
                                               __nv_bfloat16* __restrict__ Clo,
                                               int M, int K, int N)
{
    extern __shared__ char sm[];
    const uint32_t smem_base = smem_to_u32(sm);
    const int tid  = threadIdx.x;
    const int wid  = tid >> 5;
    const int lane = tid & 31;
    const int wm   = wid >> 2;
    const int wn   = wid & 3;
    const int n0 = blockIdx.x * 128;
    const int m0 = blockIdx.y * 128;

    float acc[4][4][4];
    #pragma unroll
    for (int i = 0; i < 4; i++)
        #pragma unroll
        for (int j = 0; j < 4; j++)
            #pragma unroll
            for (int q = 0; q < 4; q++) acc[i][j][q] = 0.f;

    const int NC = K / 32;

    // fill indices
    const int a_r = tid >> 1;              // A row 0..127
    const int a_p = (tid & 1) * 2;         // uint4 pos 0/2 (+1)
    const int b_r = tid >> 3;              // B k-row 0..31
    const int b_p = (tid & 7) * 2;         // uint4 pos 0..14 (+1)

    uint4 rah[2], ral[2], rbh[2], rbl[2];

    auto load_chunk = [&](int kc) {
        const __nv_bfloat16* ah = Ahi + (size_t)(m0 + a_r) * K + kc * 32 + a_p * 8;
        const __nv_bfloat16* al = Alo + (size_t)(m0 + a_r) * K + kc * 32 + a_p * 8;
        rah[0] = *(const uint4*)ah;       rah[1] = *(const uint4*)(ah + 8);
        ral[0] = *(const uint4*)al;       ral[1] = *(const uint4*)(al + 8);
        const __nv_bfloat16* bh = Bhi + (size_t)(kc * 32 + b_r) * N + n0 + b_p * 8;
        const __nv_bfloat16* bl = Blo + (size_t)(kc * 32 + b_r) * N + n0 + b_p * 8;
        rbh[0] = *(const uint4*)bh;       rbh[1] = *(const uint4*)(bh + 8);
        rbl[0] = *(const uint4*)bl;       rbl[1] = *(const uint4*)(bl + 8);
    };
    auto store_chunk = [&](int bsel) {
        char* buf = sm + bsel * BUF_BYTES;
        const uint32_t aoff = (uint32_t)a_r * A_STRB + a_p * 16;
        *(uint4*)(buf + aoff)                = rah[0];
        *(uint4*)(buf + aoff + 16)           = rah[1];
        *(uint4*)(buf + OFF_ALO + aoff)      = ral[0];
        *(uint4*)(buf + OFF_ALO + aoff + 16) = ral[1];
        const uint32_t boff = (uint32_t)b_r * B_STRB + b_p * 16;
        *(uint4*)(buf + OFF_BHI + boff)      = rbh[0];
        *(uint4*)(buf + OFF_BHI + boff + 16) = rbh[1];
        *(uint4*)(buf + OFF_BLO + boff)      = rbl[0];
        *(uint4*)(buf + OFF_BLO + boff + 16) = rbl[1];
    };

    const uint32_t a_lrow = (uint32_t)(wm * 64 + (lane & 15));
    const uint32_t a_koff = (uint32_t)(8 * (lane >> 4));
    const uint32_t b_lrow = (uint32_t)(lane & 15);
    const uint32_t b_noff = (uint32_t)(wn * 32);

    load_chunk(0);
    store_chunk(0);
    __syncthreads();

    for (int ic = 0; ic < NC; ic++) {
        const int bsel = ic & 1;
        if (ic + 1 < NC) load_chunk(ic + 1);

        const uint32_t buf = smem_base + bsel * BUF_BYTES;
        #pragma unroll
        for (int k16 = 0; k16 < 2; k16++) {
            uint32_t ah[4][4], al[4][4], bh[4][2], bl[4][2];
            #pragma unroll
            for (int mi = 0; mi < 4; mi++) {
                const uint32_t aoff = (a_lrow + mi * 16) * A_STRB
                                    + (k16 * 16 + a_koff) * 2;
                ldsm_x4(ah[mi], buf + aoff);
                ldsm_x4(al[mi], buf + OFF_ALO + aoff);
            }
            #pragma unroll
            for (int ni = 0; ni < 4; ni++) {
                const uint32_t boff = (k16 * 16 + b_lrow) * B_STRB
                                    + (b_noff + ni * 8) * 2;
                ldsm_x2_t(bh[ni], buf + OFF_BHI + boff);
                ldsm_x2_t(bl[ni], buf + OFF_BLO + boff);
            }
            #pragma unroll
            for (int mi = 0; mi < 4; mi++)
                #pragma unroll
                for (int ni = 0; ni < 4; ni++) {
                    mma16816(acc[mi][ni], ah[mi], bh[ni]);
                    mma16816(acc[mi][ni], ah[mi], bl[ni]);
                    mma16816(acc[mi][ni], al[mi], bh[ni]);
                }
        }

        if (ic + 1 < NC) store_chunk((ic + 1) & 1);
        __syncthreads();
    }

    // ---- epilogue ----
    const int g = lane >> 2;
    const int t = lane & 3;
    #pragma unroll
    for (int mi = 0; mi < 4; mi++) {
        #pragma unroll
        for (int half = 0; half < 2; half++) {
            const int m_ = m0 + wm * 64 + mi * 16 + g + half * 8;
            #pragma unroll
            for (int ni = 0; ni < 4; ni++) {
                const int n_ = n0 + wn * 32 + ni * 8 + 2 * t;
                float v0 = acc[mi][ni][half * 2 + 0] + bias[n_];
                float v1 = acc[mi][ni][half * 2 + 1] + bias[n_ + 1];
                if (GELU) {
                    v0 = 0.5f * v0 * (1.0f + erff(v0 * 0.70710678118654752f));
                    v1 = 0.5f * v1 * (1.0f + erff(v1 * 0.70710678118654752f));
                }
                if (RES) {
                    const float2 rv = *(const float2*)(Rz + (size_t)m_ * N + n_);
                    v0 += rv.x; v1 += rv.y;
                }
                if (OUTBF) {
                    __nv_bfloat16 h0, l0, h1, l1;
                    split2(v0, h0, l0); split2(v1, h1, l1);
                    *(uint32_t*)(Chi + (size_t)m_ * N + n_) = bfpack(h0, h1);
                    *(uint32_t*)(Clo + (size_t)m_ * N + n_) = bfpack(l0, l1);
                } else {
                    *(float2*)(C + (size_t)m_ * N + n_) = make_float2(v0, v1);
                }
            }
        }
    }
}

// ---------------- fused attention: 8 query rows per warp, bf16 hi/lo out ----------------
// smem: Kt[64][65], Vs[64][64], qsT[64][68], scT[64][68]
#define QT_STR 68
#define ATTN_SMEM ((64*65 + 64*64 + 64*QT_STR + 64*QT_STR) * 4)
__global__ void __launch_bounds__(256) attn_kernel(const float* __restrict__ qkv,
                                                   __nv_bfloat16* __restrict__ ohi,
                                                   __nv_bfloat16* __restrict__ olo)
{
    extern __shared__ float smf[];
    float (*Kt)[65]      = (float(*)[65])smf;
    float (*Vs)[64]      = (float(*)[64])(smf + 64*65);
    float (*qsT)[QT_STR] = (float(*)[QT_STR])(smf + 64*65 + 64*64);
    float (*scT)[QT_STR] = (float(*)[QT_STR])(smf + 64*65 + 64*64 + 64*QT_STR);

    const int tid  = threadIdx.x;
    const int warp = tid >> 5;
    const int lane = tid & 31;
    const int blk  = blockIdx.x;
    const int bh   = blk >> 4;          // / 16 rowblocks (64 rows each)
    const int rb   = blk & 15;
    const int b    = bh / Hh;
    const int h    = bh % Hh;

    const float* base = qkv + (size_t)(b * Nn) * (3 * Ww) + h * (3 * Cc);

    // q tile transposed: qsT[c][j]
    for (int i = tid; i < 64 * 64; i += 256) {
        const int j = i >> 6, c = i & 63;
        qsT[c][j] = base[(size_t)(rb * 64 + j) * (3 * Ww) + c];
    }

    const int r0 = warp * 8;
    float m_run[8], lsum[8], O0[8], O1[8];
    #pragma unroll
    for (int r = 0; r < 8; r++) { m_run[r] = -1e30f; lsum[r] = 0.f; O0[r] = 0.f; O1[r] = 0.f; }

    for (int kt = 0; kt < 16; kt++) {
        __syncthreads();
        #pragma unroll
        for (int p = 0; p < 4; p++) {
            const int flat = (p * 256 + tid) * 4;
            const int key = flat >> 6;
            const int c   = flat & 63;
            const float* kr = base + (size_t)(kt * 64 + key) * (3 * Ww) + 64 + c;
            const float4 k4 = *(const float4*)kr;
            Kt[c + 0][key] = k4.x;
            Kt[c + 1][key] = k4.y;
            Kt[c + 2][key] = k4.z;
            Kt[c + 3][key] = k4.w;
            const float* vr = base + (size_t)(kt * 64 + key) * (3 * Ww) + 128 + c;
            *(float4*)&Vs[key][c] = *(const float4*)vr;
        }
        __syncthreads();

        float s0[8], s1[8];
        #pragma unroll
        for (int r = 0; r < 8; r++) { s0[r] = 0.f; s1[r] = 0.f; }
        #pragma unroll 4
        for (int c = 0; c < 64; c++) {
            const float k0 = Kt[c][lane];
            const float k1 = Kt[c][lane + 32];
            const float4 qa = *(const float4*)&qsT[c][r0];
            const float4 qb = *(const float4*)&qsT[c][r0 + 4];
            const float q[8] = {qa.x, qa.y, qa.z, qa.w, qb.x, qb.y, qb.z, qb.w};
            #pragma unroll
            for (int r = 0; r < 8; r++) {
                s0[r] = fmaf(q[r], k0, s0[r]);
                s1[r] = fmaf(q[r], k1, s1[r]);
            }
        }
        float p0v[8], p1v[8];
        #pragma unroll
        for (int r = 0; r < 8; r++) {
            const float a = s0[r] * 0.125f;
            const float bq = s1[r] * 0.125f;
            float mt = fmaxf(a, bq);
            #pragma unroll
            for (int o = 16; o > 0; o >>= 1)
                mt = fmaxf(mt, __shfl_xor_sync(0xffffffffu, mt, o));
            const float mn = fmaxf(m_run[r], mt);
            const float alpha = __expf(m_run[r] - mn);
            const float p0 = __expf(a - mn);
            const float p1 = __expf(bq - mn);
            lsum[r] = lsum[r] * alpha + p0 + p1;
            O0[r] *= alpha; O1[r] *= alpha;
            p0v[r] = p0; p1v[r] = p1;
            m_run[r] = mn;
        }
        *(float4*)&scT[lane][r0]          = make_float4(p0v[0], p0v[1], p0v[2], p0v[3]);
        *(float4*)&scT[lane][r0 + 4]      = make_float4(p0v[4], p0v[5], p0v[6], p0v[7]);
        *(float4*)&scT[lane + 32][r0]     = make_float4(p1v[0], p1v[1], p1v[2], p1v[3]);
        *(float4*)&scT[lane + 32][r0 + 4] = make_float4(p1v[4], p1v[5], p1v[6], p1v[7]);
        __syncwarp();
        #pragma unroll 4
        for (int s_ = 0; s_ < 64; s_++) {
            const float v0 = Vs[s_][lane];
            const float v1 = Vs[s_][lane + 32];
            const float4 pa = *(const float4*)&scT[s_][r0];
            const float4 pb = *(const float4*)&scT[s_][r0 + 4];
            const float p[8] = {pa.x, pa.y, pa.z, pa.w, pb.x, pb.y, pb.z, pb.w};
            #pragma unroll
            for (int r = 0; r < 8; r++) {
                O0[r] = fmaf(p[r], v0, O0[r]);
                O1[r] = fmaf(p[r], v1, O1[r]);
            }
        }
    }

    #pragma unroll
    for (int r = 0; r < 8; r++) {
        float lt = lsum[r];
        #pragma unroll
        for (int o = 16; o > 0; o >>= 1)
            lt += __shfl_xor_sync(0xffffffffu, lt, o);
        const float inv = 1.f / lt;
        const size_t off = (size_t)(b * Nn + rb * 64 + r0 + r) * Ww + h * Cc;
        const float o0 = O0[r] * inv, o1 = O1[r] * inv;
        __nv_bfloat16 h0, l0, h1, l1;
        split2(o0, h0, l0); split2(o1, h1, l1);
        ohi[off + lane]      = h0;  olo[off + lane]      = l0;
        ohi[off + lane + 32] = h1;  olo[off + lane + 32] = l1;
    }
}

// ---------------- launcher ----------------
extern "C" void kernel_launch(void* const* d_in, const int* in_sizes, int n_in,
                              void* d_out, int out_size)
{
    const float* x    = (const float*)d_in[0];
    const float* Wqkv = (const float*)d_in[1];
    const float* bqkv = (const float*)d_in[2];
    const float* Wo   = (const float*)d_in[3];
    const float* bo   = (const float*)d_in[4];
    const float* Wfc  = (const float*)d_in[5];
    const float* bfc  = (const float*)d_in[6];
    const float* Wpr  = (const float*)d_in[7];
    const float* bpr  = (const float*)d_in[8];
    const float* g1   = (const float*)d_in[9];
    const float* b1   = (const float*)d_in[10];
    const float* g2   = (const float*)d_in[11];
    const float* b2   = (const float*)d_in[12];

    float* h = (float*)d_out;

    float* pqkv;
    __nv_bfloat16 *pyhi, *pylo, *pahi, *palo, *pfchi, *pfclo;
    __nv_bfloat16 *wq_hi, *wq_lo, *wo_hi, *wo_lo, *wf_hi, *wf_lo, *wp_hi, *wp_lo;
    cudaGetSymbolAddress((void**)&pqkv,  g_qkv);
    cudaGetSymbolAddress((void**)&pyhi,  g_yhi);
    cudaGetSymbolAddress((void**)&pylo,  g_ylo);
    cudaGetSymbolAddress((void**)&pahi,  g_ahi);
    cudaGetSymbolAddress((void**)&palo,  g_alo);
    cudaGetSymbolAddress((void**)&pfchi, g_fchi);
    cudaGetSymbolAddress((void**)&pfclo, g_fclo);
    cudaGetSymbolAddress((void**)&wq_hi, g_wqkv_hi);
    cudaGetSymbolAddress((void**)&wq_lo, g_wqkv_lo);
    cudaGetSymbolAddress((void**)&wo_hi, g_wo_hi);
    cudaGetSymbolAddress((void**)&wo_lo, g_wo_lo);
    cudaGetSymbolAddress((void**)&wf_hi, g_wfc_hi);
    cudaGetSymbolAddress((void**)&wf_lo, g_wfc_lo);
    cudaGetSymbolAddress((void**)&wp_hi, g_wpr_hi);
    cudaGetSymbolAddress((void**)&wp_lo, g_wpr_lo);

    cudaFuncSetAttribute(gemm_tc<0,0,0>, cudaFuncAttributeMaxDynamicSharedMemorySize, GEMM_SMEM);
    cudaFuncSetAttribute(gemm_tc<1,0,0>, cudaFuncAttributeMaxDynamicSharedMemorySize, GEMM_SMEM);
    cudaFuncSetAttribute(gemm_tc<0,1,1>, cudaFuncAttributeMaxDynamicSharedMemorySize, GEMM_SMEM);
    cudaFuncSetAttribute(attn_kernel,    cudaFuncAttributeMaxDynamicSharedMemorySize, ATTN_SMEM);

    cudaMemcpyAsync(h, x, (size_t)ROWS * Ww * sizeof(float), cudaMemcpyDeviceToDevice);

    // convert all weights once
    {
        int n4;
        n4 = Lnum * Ww * 3 * Ww / 4;
        cvt_kernel<<<(n4 + 255) / 256, 256>>>((const float4*)Wqkv, (uint2*)wq_hi, (uint2*)wq_lo, n4);
        n4 = Lnum * Ww * Ww / 4;
        cvt_kernel<<<(n4 + 255) / 256, 256>>>((const float4*)Wo,   (uint2*)wo_hi, (uint2*)wo_lo, n4);
        n4 = Lnum * Ww * 4 * Ww / 4;
        cvt_kernel<<<(n4 + 255) / 256, 256>>>((const float4*)Wfc,  (uint2*)wf_hi, (uint2*)wf_lo, n4);
        n4 = Lnum * 4 * Ww * Ww / 4;
        cvt_kernel<<<(n4 + 255) / 256, 256>>>((const float4*)Wpr,  (uint2*)wp_hi, (uint2*)wp_lo, n4);
    }

    for (int l = 0; l < Lnum; l++) {
        const size_t oq = (size_t)l * Ww * 3 * Ww;
        const size_t oo = (size_t)l * Ww * Ww;
        const size_t of = (size_t)l * Ww * 4 * Ww;
        const size_t op = (size_t)l * 4 * Ww * Ww;
        const float* bq  = bqkv + (size_t)l * 3 * Ww;
        const float* bo_ = bo   + (size_t)l * Ww;
        const float* bf  = bfc  + (size_t)l * 4 * Ww;
        const float* bp  = bpr  + (size_t)l * Ww;

        // LN1 -> bf16 hi/lo
        ln_kernel<<<ROWS, 256>>>(h, g1 + l * Ww, b1 + l * Ww, pyhi, pylo);
        // qkv = y @ Wqkv + bqkv   (fp32 out)
        gemm_tc<0,0,0><<<dim3(3 * Ww / 128, ROWS / 128), 256, GEMM_SMEM>>>(
            pyhi, pylo, wq_hi + oq, wq_lo + oq, bq, nullptr,
            pqkv, nullptr, nullptr, ROWS, Ww, 3 * Ww);
        // attention -> bf16 hi/lo
        attn_kernel<<<Bb * Hh * (Nn / 64), 256, ATTN_SMEM>>>(pqkv, pahi, palo);
        // h = h + attn @ Wo + bo
        gemm_tc<1,0,0><<<dim3(Ww / 128, ROWS / 128), 256, GEMM_SMEM>>>(
            pahi, palo, wo_hi + oo, wo_lo + oo, bo_, h,
            h, nullptr, nullptr, ROWS, Ww, Ww);
        // LN2 -> bf16 hi/lo
        ln_kernel<<<ROWS, 256>>>(h, g2 + l * Ww, b2 + l * Ww, pyhi, pylo);
        // fc = gelu(y @ Wfc + bfc) -> bf16 hi/lo
        gemm_tc<0,1,1><<<dim3(4 * Ww / 128, ROWS / 128), 256, GEMM_SMEM>>>(
            pyhi, pylo, wf_hi + of, wf_lo + of, bf, nullptr,
            nullptr, pfchi, pfclo, ROWS, Ww, 4 * Ww);
        // h = h + fc @ Wpr + bpr
        gemm_tc<1,0,0><<<dim3(Ww / 128, ROWS / 128), 256, GEMM_SMEM>>>(
            pfchi, pfclo, wp_hi + op, wp_lo + op, bp, h,
            h, nullptr, nullptr, ROWS, 4 * Ww, Ww);
    }
}

// round 5
// speedup vs baseline: 3.1011x; 1.3002x over previous
#include <cuda_runtime.h>
#include <cuda_bf16.h>
#include <math.h>
#include <stdint.h>

// Problem constants
#define Lnum 8
#define Bb   8
#define Nn   1024
#define Ww   768
#define Hh   12
#define Cc   64
#define ROWS (Bb*Nn)          // 8192 token rows

// ---------------- scratch (no cudaMalloc allowed) ----------------
__device__ __nv_bfloat16 g_qkvhi[ROWS * 3 * Ww], g_qkvlo[ROWS * 3 * Ww];
__device__ __nv_bfloat16 g_yhi[ROWS * Ww],  g_ylo[ROWS * Ww];
__device__ __nv_bfloat16 g_ahi[ROWS * Ww],  g_alo[ROWS * Ww];
__device__ __nv_bfloat16 g_fchi[ROWS * 4 * Ww], g_fclo[ROWS * 4 * Ww];
__device__ __nv_bfloat16 g_wqkv_hi[Lnum * Ww * 3 * Ww], g_wqkv_lo[Lnum * Ww * 3 * Ww];
__device__ __nv_bfloat16 g_wo_hi  [Lnum * Ww * Ww],     g_wo_lo  [Lnum * Ww * Ww];
__device__ __nv_bfloat16 g_wfc_hi [Lnum * Ww * 4 * Ww], g_wfc_lo [Lnum * Ww * 4 * Ww];
__device__ __nv_bfloat16 g_wpr_hi [Lnum * 4 * Ww * Ww], g_wpr_lo [Lnum * 4 * Ww * Ww];

// =================== portable PTX helpers ===================
__device__ __forceinline__ uint32_t smem_to_u32(const void* smem_ptr) {
    uint32_t addr;
    asm("{ .reg .u64 tmp; cvta.to.shared.u64 tmp, %1; cvt.u32.u64 %0, tmp; }"
        : "=r"(addr) : "l"(smem_ptr));
    return addr;
}
__device__ __forceinline__ void ldsm_x4(uint32_t* r, uint32_t addr) {
    asm volatile("ldmatrix.sync.aligned.m8n8.x4.shared.b16 {%0,%1,%2,%3}, [%4];"
        : "=r"(r[0]), "=r"(r[1]), "=r"(r[2]), "=r"(r[3]) : "r"(addr));
}
__device__ __forceinline__ void ldsm_x2_t(uint32_t* r, uint32_t addr) {
    asm volatile("ldmatrix.sync.aligned.m8n8.x2.trans.shared.b16 {%0,%1}, [%2];"
        : "=r"(r[0]), "=r"(r[1]) : "r"(addr));
}
__device__ __forceinline__ void mma16816(float* d, const uint32_t* a, const uint32_t* b) {
    asm volatile(
        "mma.sync.aligned.m16n8k16.row.col.f32.bf16.bf16.f32 "
        "{%0,%1,%2,%3}, {%4,%5,%6,%7}, {%8,%9}, {%0,%1,%2,%3};\n"
        : "+f"(d[0]), "+f"(d[1]), "+f"(d[2]), "+f"(d[3])
        : "r"(a[0]), "r"(a[1]), "r"(a[2]), "r"(a[3]), "r"(b[0]), "r"(b[1]));
}
__device__ __forceinline__ void cp16(uint32_t s, const void* g) {
    asm volatile("cp.async.ca.shared.global [%0], [%1], 16;" :: "r"(s), "l"(g));
}
#define CP_COMMIT() asm volatile("cp.async.commit_group;")
#define CP_WAIT1()  asm volatile("cp.async.wait_group 1;")
#define CP_WAIT0()  asm volatile("cp.async.wait_group 0;")

__device__ __forceinline__ uint32_t bfpack(__nv_bfloat16 a, __nv_bfloat16 b) {
    uint16_t ua = *(uint16_t*)&a, ub = *(uint16_t*)&b;
    return (uint32_t)ua | ((uint32_t)ub << 16);
}
__device__ __forceinline__ void split2(float x, __nv_bfloat16& h, __nv_bfloat16& l) {
    h = __float2bfloat16(x);
    l = __float2bfloat16(x - __bfloat162float(h));
}

// ---------------- weight conversion ----------------
__global__ void __launch_bounds__(256) cvt_kernel(const float4* __restrict__ src,
                                                  uint2* __restrict__ hi,
                                                  uint2* __restrict__ lo,
                                                  int n4)
{
    int i = blockIdx.x * 256 + threadIdx.x;
    if (i >= n4) return;
    const float4 x = src[i];
    __nv_bfloat16 h0, h1, h2, h3, l0, l1, l2, l3;
    split2(x.x, h0, l0); split2(x.y, h1, l1);
    split2(x.z, h2, l2); split2(x.w, h3, l3);
    hi[i] = make_uint2(bfpack(h0, h1), bfpack(h2, h3));
    lo[i] = make_uint2(bfpack(l0, l1), bfpack(l2, l3));
}

// ---------------- LayerNorm ----------------
__global__ void __launch_bounds__(256) ln_kernel(const float* __restrict__ x,
                                                 const float* __restrict__ g,
                                                 const float* __restrict__ b,
                                                 __nv_bfloat16* __restrict__ yhi,
                                                 __nv_bfloat16* __restrict__ ylo)
{
    __shared__ float row[Ww];
    __shared__ float red[256];
    const int r   = blockIdx.x;
    const int tid = threadIdx.x;
    const float* xr = x + (size_t)r * Ww;

    float s = 0.f;
    #pragma unroll
    for (int i = tid; i < Ww; i += 256) { float v = xr[i]; row[i] = v; s += v; }
    red[tid] = s; __syncthreads();
    for (int o = 128; o > 0; o >>= 1) { if (tid < o) red[tid] += red[tid + o]; __syncthreads(); }
    const float mean = red[0] * (1.f / Ww);
    __syncthreads();

    float s2 = 0.f;
    #pragma unroll
    for (int i = tid; i < Ww; i += 256) { float d = row[i] - mean; s2 += d * d; }
    red[tid] = s2; __syncthreads();
    for (int o = 128; o > 0; o >>= 1) { if (tid < o) red[tid] += red[tid + o]; __syncthreads(); }
    const float var = red[0] * (1.f / Ww);
    const float w = rsqrtf(var + 1e-5f);

    #pragma unroll
    for (int i = tid; i < Ww; i += 256) {
        const float v = (row[i] - mean) * w * g[i] + b[i];
        __nv_bfloat16 h, l; split2(v, h, l);
        yhi[(size_t)r * Ww + i] = h;
        ylo[(size_t)r * Ww + i] = l;
    }
}

// =================== bf16x3 tensor-core GEMM (unchanged from R4) ===================
#define A_STRB 80
#define B_STRB 272
#define A_BYTES (128 * A_STRB)
#define B_BYTES (32 * B_STRB)
#define OFF_ALO A_BYTES
#define OFF_BHI (2*A_BYTES)
#define OFF_BLO (2*A_BYTES + B_BYTES)
#define BUF_BYTES (2*A_BYTES + 2*B_BYTES)
#define GEMM_SMEM (2 * BUF_BYTES)

template<int RES, int GELU, int OUTBF>
__global__ void __launch_bounds__(256) gemm_tc(const __nv_bfloat16* __restrict__ Ahi,
                                               const __nv_bfloat16* __restrict__ Alo,
                                               const __nv_bfloat16* __restrict__ Bhi,
                                               const __nv_bfloat16* __restrict__ Blo,
                                               const float* __restrict__ bias,
                                               const float* __restrict__ Rz,
                                               float* __restrict__ C,
                                               __nv_bfloat16* __restrict__ Chi,
                                               __nv_bfloat16* __restrict__ Clo,
                                               int M, int K, int N)
{
    extern __shared__ char sm[];
    const uint32_t smem_base = smem_to_u32(sm);
    const int tid  = threadIdx.x;
    const int wid  = tid >> 5;
    const int lane = tid & 31;
    const int wm   = wid >> 2;
    const int wn   = wid & 3;
    const int n0 = blockIdx.x * 128;
    const int m0 = blockIdx.y * 128;

    float acc[4][4][4];
    #pragma unroll
    for (int i = 0; i < 4; i++)
        #pragma unroll
        for (int j = 0; j < 4; j++)
            #pragma unroll
            for (int q = 0; q < 4; q++) acc[i][j][q] = 0.f;

    const int NC = K / 32;

    const int a_r = tid >> 1;
    const int a_p = (tid & 1) * 2;
    const int b_r = tid >> 3;
    const int b_p = (tid & 7) * 2;

    uint4 rah[2], ral[2], rbh[2], rbl[2];

    auto load_chunk = [&](int kc) {
        const __nv_bfloat16* ah = Ahi + (size_t)(m0 + a_r) * K + kc * 32 + a_p * 8;
        const __nv_bfloat16* al = Alo + (size_t)(m0 + a_r) * K + kc * 32 + a_p * 8;
        rah[0] = *(const uint4*)ah;       rah[1] = *(const uint4*)(ah + 8);
        ral[0] = *(const uint4*)al;       ral[1] = *(const uint4*)(al + 8);
        const __nv_bfloat16* bh = Bhi + (size_t)(kc * 32 + b_r) * N + n0 + b_p * 8;
        const __nv_bfloat16* bl = Blo + (size_t)(kc * 32 + b_r) * N + n0 + b_p * 8;
        rbh[0] = *(const uint4*)bh;       rbh[1] = *(const uint4*)(bh + 8);
        rbl[0] = *(const uint4*)bl;       rbl[1] = *(const uint4*)(bl + 8);
    };
    auto store_chunk = [&](int bsel) {
        char* buf = sm + bsel * BUF_BYTES;
        const uint32_t aoff = (uint32_t)a_r * A_STRB + a_p * 16;
        *(uint4*)(buf + aoff)                = rah[0];
        *(uint4*)(buf + aoff + 16)           = rah[1];
        *(uint4*)(buf + OFF_ALO + aoff)      = ral[0];
        *(uint4*)(buf + OFF_ALO + aoff + 16) = ral[1];
        const uint32_t boff = (uint32_t)b_r * B_STRB + b_p * 16;
        *(uint4*)(buf + OFF_BHI + boff)      = rbh[0];
        *(uint4*)(buf + OFF_BHI + boff + 16) = rbh[1];
        *(uint4*)(buf + OFF_BLO + boff)      = rbl[0];
        *(uint4*)(buf + OFF_BLO + boff + 16) = rbl[1];
    };

    const uint32_t a_lrow = (uint32_t)(wm * 64 + (lane & 15));
    const uint32_t a_koff = (uint32_t)(8 * (lane >> 4));
    const uint32_t b_lrow = (uint32_t)(lane & 15);
    const uint32_t b_noff = (uint32_t)(wn * 32);

    load_chunk(0);
    store_chunk(0);
    __syncthreads();

    for (int ic = 0; ic < NC; ic++) {
        const int bsel = ic & 1;
        if (ic + 1 < NC) load_chunk(ic + 1);

        const uint32_t buf = smem_base + bsel * BUF_BYTES;
        #pragma unroll
        for (int k16 = 0; k16 < 2; k16++) {
            uint32_t ah[4][4], al[4][4], bh[4][2], bl[4][2];
            #pragma unroll
            for (int mi = 0; mi < 4; mi++) {
                const uint32_t aoff = (a_lrow + mi * 16) * A_STRB
                                    + (k16 * 16 + a_koff) * 2;
                ldsm_x4(ah[mi], buf + aoff);
                ldsm_x4(al[mi], buf + OFF_ALO + aoff);
            }
            #pragma unroll
            for (int ni = 0; ni < 4; ni++) {
                const uint32_t boff = (k16 * 16 + b_lrow) * B_STRB
                                    + (b_noff + ni * 8) * 2;
                ldsm_x2_t(bh[ni], buf + OFF_BHI + boff);
                ldsm_x2_t(bl[ni], buf + OFF_BLO + boff);
            }
            #pragma unroll
            for (int mi = 0; mi < 4; mi++)
                #pragma unroll
                for (int ni = 0; ni < 4; ni++) {
                    mma16816(acc[mi][ni], ah[mi], bh[ni]);
                    mma16816(acc[mi][ni], ah[mi], bl[ni]);
                    mma16816(acc[mi][ni], al[mi], bh[ni]);
                }
        }

        if (ic + 1 < NC) store_chunk((ic + 1) & 1);
        __syncthreads();
    }

    const int g = lane >> 2;
    const int t = lane & 3;
    #pragma unroll
    for (int mi = 0; mi < 4; mi++) {
        #pragma unroll
        for (int half = 0; half < 2; half++) {
            const int m_ = m0 + wm * 64 + mi * 16 + g + half * 8;
            #pragma unroll
            for (int ni = 0; ni < 4; ni++) {
                const int n_ = n0 + wn * 32 + ni * 8 + 2 * t;
                float v0 = acc[mi][ni][half * 2 + 0] + bias[n_];
                float v1 = acc[mi][ni][half * 2 + 1] + bias[n_ + 1];
                if (GELU) {
                    v0 = 0.5f * v0 * (1.0f + erff(v0 * 0.70710678118654752f));
                    v1 = 0.5f * v1 * (1.0f + erff(v1 * 0.70710678118654752f));
                }
                if (RES) {
                    const float2 rv = *(const float2*)(Rz + (size_t)m_ * N + n_);
                    v0 += rv.x; v1 += rv.y;
                }
                if (OUTBF) {
                    __nv_bfloat16 h0, l0, h1, l1;
                    split2(v0, h0, l0); split2(v1, h1, l1);
                    *(uint32_t*)(Chi + (size_t)m_ * N + n_) = bfpack(h0, h1);
                    *(uint32_t*)(Clo + (size_t)m_ * N + n_) = bfpack(l0, l1);
                } else {
                    *(float2*)(C + (size_t)m_ * N + n_) = make_float2(v0, v1);
                }
            }
        }
    }
}

// =================== tensor-core flash attention (bf16x3) ===================
// block: 128 q rows of one (b,h). 8 warps x 16 rows. Key tiles of 64.
// smem: Qhi/Qlo [128][72 bf16] stride 144B; double-buffered K/V hi/lo [64][72] each.
#define AT_STR 144
#define AT_OFF_QLO (128*AT_STR)
#define AT_OFF_KV  (2*128*AT_STR)          // 36864
#define AT_BUF     (4*64*AT_STR)           // 36864 per buffer
#define AT_KHI 0
#define AT_KLO (64*AT_STR)
#define AT_VHI (2*64*AT_STR)
#define AT_VLO (3*64*AT_STR)
#define ATTN_SMEM (AT_OFF_KV + 2*AT_BUF)   // 110592

__global__ void __launch_bounds__(256) attn_tc(const __nv_bfloat16* __restrict__ qhi,
                                               const __nv_bfloat16* __restrict__ qlo,
                                               __nv_bfloat16* __restrict__ ohi,
                                               __nv_bfloat16* __restrict__ olo)
{
    extern __shared__ char sm[];
    const uint32_t sb = smem_to_u32(sm);
    const int tid  = threadIdx.x;
    const int warp = tid >> 5;
    const int lane = tid & 31;
    const int g    = lane >> 2;
    const int t    = lane & 3;
    const int blk  = blockIdx.x;
    const int bh   = blk >> 3;
    const int rb   = blk & 7;
    const int b    = bh / Hh;
    const int h    = bh % Hh;
    const int rowbase = b * Nn + rb * 128;
    const int colq = h * 3 * Cc;

    // ---- issue Q loads (128 rows x 8 chunks x 2 arrays) ----
    #pragma unroll
    for (int i = 0; i < 4; i++) {
        const int flat = tid + i * 256;
        const int row = flat >> 3, c8 = flat & 7;
        const size_t goff = (size_t)(rowbase + row) * (3 * Ww) + colq + c8 * 8;
        cp16(sb + row * AT_STR + c8 * 16, qhi + goff);
        cp16(sb + AT_OFF_QLO + row * AT_STR + c8 * 16, qlo + goff);
    }
    // ---- issue K/V tile 0 ----
    auto issue_kv = [&](int kt, int bsel) {
        const uint32_t kvb = sb + AT_OFF_KV + bsel * AT_BUF;
        #pragma unroll
        for (int i = 0; i < 2; i++) {
            const int flat = tid + i * 256;
            const int row = flat >> 3, c8 = flat & 7;
            const size_t go = (size_t)(b * Nn + kt * 64 + row) * (3 * Ww) + colq + c8 * 8;
            const uint32_t so = row * AT_STR + c8 * 16;
            cp16(kvb + AT_KHI + so, qhi + go + 64);
            cp16(kvb + AT_KLO + so, qlo + go + 64);
            cp16(kvb + AT_VHI + so, qhi + go + 128);
            cp16(kvb + AT_VLO + so, qlo + go + 128);
        }
    };
    issue_kv(0, 0);
    CP_COMMIT();

    float m0r = -1e30f, m1r = -1e30f, l0r = 0.f, l1r = 0.f;
    float O[8][4];
    #pragma unroll
    for (int j = 0; j < 8; j++)
        #pragma unroll
        for (int q = 0; q < 4; q++) O[j][q] = 0.f;

    // ldmatrix lane-address components
    const uint32_t q_lrow = (uint32_t)(16 * warp + (lane & 15));
    const uint32_t q_koff = (uint32_t)(8 * (lane >> 4));
    const int k_nrow = (lane & 7) + ((lane >> 4) << 3);   // rows n0..7 twice -> +8
    const int k_koff = ((lane >> 3) & 1) * 8;
    const int v_krow = lane & 15;

    for (int kt = 0; kt < 16; kt++) {
        if (kt + 1 < 16) { issue_kv(kt + 1, (kt + 1) & 1); CP_COMMIT(); CP_WAIT1(); }
        else CP_WAIT0();
        __syncthreads();

        const uint32_t kvb = sb + AT_OFF_KV + (kt & 1) * AT_BUF;

        // ---- S = Q K^T (3-term) ----
        float s[8][4];
        #pragma unroll
        for (int j = 0; j < 8; j++)
            #pragma unroll
            for (int q = 0; q < 4; q++) s[j][q] = 0.f;

        #pragma unroll
        for (int k16 = 0; k16 < 4; k16++) {
            uint32_t ah[4], al[4];
            const uint32_t qo = q_lrow * AT_STR + (k16 * 16 + q_koff) * 2;
            ldsm_x4(ah, sb + qo);
            ldsm_x4(al, sb + AT_OFF_QLO + qo);
            #pragma unroll
            for (int jj = 0; jj < 4; jj++) {
                uint32_t kh[4], kl[4];
                const uint32_t ko = (uint32_t)(16 * jj + k_nrow) * AT_STR
                                  + (k16 * 16 + k_koff) * 2;
                ldsm_x4(kh, kvb + AT_KHI + ko);
                ldsm_x4(kl, kvb + AT_KLO + ko);
                mma16816(s[2*jj],   ah, &kh[0]);
                mma16816(s[2*jj],   ah, &kl[0]);
                mma16816(s[2*jj],   al, &kh[0]);
                mma16816(s[2*jj+1], ah, &kh[2]);
                mma16816(s[2*jj+1], ah, &kl[2]);
                mma16816(s[2*jj+1], al, &kh[2]);
            }
        }

        // ---- online softmax (fp32) ----
        float mx0 = -1e30f, mx1 = -1e30f;
        #pragma unroll
        for (int j = 0; j < 8; j++) {
            s[j][0] *= 0.125f; s[j][1] *= 0.125f; s[j][2] *= 0.125f; s[j][3] *= 0.125f;
            mx0 = fmaxf(mx0, fmaxf(s[j][0], s[j][1]));
            mx1 = fmaxf(mx1, fmaxf(s[j][2], s[j][3]));
        }
        mx0 = fmaxf(mx0, __shfl_xor_sync(0xffffffffu, mx0, 1));
        mx0 = fmaxf(mx0, __shfl_xor_sync(0xffffffffu, mx0, 2));
        mx1 = fmaxf(mx1, __shfl_xor_sync(0xffffffffu, mx1, 1));
        mx1 = fmaxf(mx1, __shfl_xor_sync(0xffffffffu, mx1, 2));
        const float mn0 = fmaxf(m0r, mx0);
        const float mn1 = fmaxf(m1r, mx1);
        const float al0 = __expf(m0r - mn0);
        const float al1 = __expf(m1r - mn1);
        m0r = mn0; m1r = mn1;
        float ps0 = 0.f, ps1 = 0.f;
        #pragma unroll
        for (int j = 0; j < 8; j++) {
            s[j][0] = __expf(s[j][0] - mn0);
            s[j][1] = __expf(s[j][1] - mn0);
            s[j][2] = __expf(s[j][2] - mn1);
            s[j][3] = __expf(s[j][3] - mn1);
            ps0 += s[j][0] + s[j][1];
            ps1 += s[j][2] + s[j][3];
        }
        l0r = l0r * al0 + ps0;
        l1r = l1r * al1 + ps1;
        #pragma unroll
        for (int j = 0; j < 8; j++) {
            O[j][0] *= al0; O[j][1] *= al0; O[j][2] *= al1; O[j][3] *= al1;
        }

        // ---- O += P V (3-term); P fragments direct from accumulator layout ----
        #pragma unroll
        for (int kk = 0; kk < 4; kk++) {
            uint32_t aph[4], apl[4];
            #pragma unroll
            for (int q2 = 0; q2 < 2; q2++) {     // q2: 0 = rows g (c0,c1), 1 = rows g+8 (c2,c3)
                #pragma unroll
                for (int jj = 0; jj < 2; jj++) { // jj: which n-tile of the pair
                    const int j = 2 * kk + jj;
                    __nv_bfloat16 h0, l0, h1, l1;
                    split2(s[j][2*q2 + 0], h0, l0);
                    split2(s[j][2*q2 + 1], h1, l1);
                    aph[jj * 2 + q2] = bfpack(h0, h1);
                    apl[jj * 2 + q2] = bfpack(l0, l1);
                }
            }
            #pragma unroll
            for (int j = 0; j < 8; j++) {
                uint32_t vh[2], vl[2];
                const uint32_t vo = (uint32_t)(kk * 16 + v_krow) * AT_STR + (8 * j) * 2;
                ldsm_x2_t(vh, kvb + AT_VHI + vo);
                ldsm_x2_t(vl, kvb + AT_VLO + vo);
                mma16816(O[j], aph, vh);
                mma16816(O[j], aph, vl);
                mma16816(O[j], apl, vh);
            }
        }
        __syncthreads();
    }

    // ---- finalize ----
    l0r += __shfl_xor_sync(0xffffffffu, l0r, 1);
    l0r += __shfl_xor_sync(0xffffffffu, l0r, 2);
    l1r += __shfl_xor_sync(0xffffffffu, l1r, 1);
    l1r += __shfl_xor_sync(0xffffffffu, l1r, 2);
    const float inv0 = 1.f / l0r;
    const float inv1 = 1.f / l1r;
    const int row0 = rowbase + 16 * warp + g;
    const int row1 = row0 + 8;
    #pragma unroll
    for (int j = 0; j < 8; j++) {
        const int col = h * Cc + 8 * j + 2 * t;
        float v0 = O[j][0] * inv0, v1 = O[j][1] * inv0;
        float w0 = O[j][2] * inv1, w1 = O[j][3] * inv1;
        __nv_bfloat16 h0, l0, h1, l1;
        split2(v0, h0, l0); split2(v1, h1, l1);
        *(uint32_t*)(ohi + (size_t)row0 * Ww + col) = bfpack(h0, h1);
        *(uint32_t*)(olo + (size_t)row0 * Ww + col) = bfpack(l0, l1);
        split2(w0, h0, l0); split2(w1, h1, l1);
        *(uint32_t*)(ohi + (size_t)row1 * Ww + col) = bfpack(h0, h1);
        *(uint32_t*)(olo + (size_t)row1 * Ww + col) = bfpack(l0, l1);
    }
}

// ---------------- launcher ----------------
extern "C" void kernel_launch(void* const* d_in, const int* in_sizes, int n_in,
                              void* d_out, int out_size)
{
    const float* x    = (const float*)d_in[0];
    const float* Wqkv = (const float*)d_in[1];
    const float* bqkv = (const float*)d_in[2];
    const float* Wo   = (const float*)d_in[3];
    const float* bo   = (const float*)d_in[4];
    const float* Wfc  = (const float*)d_in[5];
    const float* bfc  = (const float*)d_in[6];
    const float* Wpr  = (const float*)d_in[7];
    const float* bpr  = (const float*)d_in[8];
    const float* g1   = (const float*)d_in[9];
    const float* b1   = (const float*)d_in[10];
    const float* g2   = (const float*)d_in[11];
    const float* b2   = (const float*)d_in[12];

    float* h = (float*)d_out;

    __nv_bfloat16 *pqhi, *pqlo, *pyhi, *pylo, *pahi, *palo, *pfchi, *pfclo;
    __nv_bfloat16 *wq_hi, *wq_lo, *wo_hi, *wo_lo, *wf_hi, *wf_lo, *wp_hi, *wp_lo;
    cudaGetSymbolAddress((void**)&pqhi,  g_qkvhi);
    cudaGetSymbolAddress((void**)&pqlo,  g_qkvlo);
    cudaGetSymbolAddress((void**)&pyhi,  g_yhi);
    cudaGetSymbolAddress((void**)&pylo,  g_ylo);
    cudaGetSymbolAddress((void**)&pahi,  g_ahi);
    cudaGetSymbolAddress((void**)&palo,  g_alo);
    cudaGetSymbolAddress((void**)&pfchi, g_fchi);
    cudaGetSymbolAddress((void**)&pfclo, g_fclo);
    cudaGetSymbolAddress((void**)&wq_hi, g_wqkv_hi);
    cudaGetSymbolAddress((void**)&wq_lo, g_wqkv_lo);
    cudaGetSymbolAddress((void**)&wo_hi, g_wo_hi);
    cudaGetSymbolAddress((void**)&wo_lo, g_wo_lo);
    cudaGetSymbolAddress((void**)&wf_hi, g_wfc_hi);
    cudaGetSymbolAddress((void**)&wf_lo, g_wfc_lo);
    cudaGetSymbolAddress((void**)&wp_hi, g_wpr_hi);
    cudaGetSymbolAddress((void**)&wp_lo, g_wpr_lo);

    cudaFuncSetAttribute(gemm_tc<0,0,1>, cudaFuncAttributeMaxDynamicSharedMemorySize, GEMM_SMEM);
    cudaFuncSetAttribute(gemm_tc<1,0,0>, cudaFuncAttributeMaxDynamicSharedMemorySize, GEMM_SMEM);
    cudaFuncSetAttribute(gemm_tc<0,1,1>, cudaFuncAttributeMaxDynamicSharedMemorySize, GEMM_SMEM);
    cudaFuncSetAttribute(attn_tc,        cudaFuncAttributeMaxDynamicSharedMemorySize, ATTN_SMEM);

    cudaMemcpyAsync(h, x, (size_t)ROWS * Ww * sizeof(float), cudaMemcpyDeviceToDevice);

    {
        int n4;
        n4 = Lnum * Ww * 3 * Ww / 4;
        cvt_kernel<<<(n4 + 255) / 256, 256>>>((const float4*)Wqkv, (uint2*)wq_hi, (uint2*)wq_lo, n4);
        n4 = Lnum * Ww * Ww / 4;
        cvt_kernel<<<(n4 + 255) / 256, 256>>>((const float4*)Wo,   (uint2*)wo_hi, (uint2*)wo_lo, n4);
        n4 = Lnum * Ww * 4 * Ww / 4;
        cvt_kernel<<<(n4 + 255) / 256, 256>>>((const float4*)Wfc,  (uint2*)wf_hi, (uint2*)wf_lo, n4);
        n4 = Lnum * 4 * Ww * Ww / 4;
        cvt_kernel<<<(n4 + 255) / 256, 256>>>((const float4*)Wpr,  (uint2*)wp_hi, (uint2*)wp_lo, n4);
    }

    for (int l = 0; l < Lnum; l++) {
        const size_t oq = (size_t)l * Ww * 3 * Ww;
        const size_t oo = (size_t)l * Ww * Ww;
        const size_t of = (size_t)l * Ww * 4 * Ww;
        const size_t op = (size_t)l * 4 * Ww * Ww;
        const float* bq  = bqkv + (size_t)l * 3 * Ww;
        const float* bo_ = bo   + (size_t)l * Ww;
        const float* bf  = bfc  + (size_t)l * 4 * Ww;
        const float* bp  = bpr  + (size_t)l * Ww;

        ln_kernel<<<ROWS, 256>>>(h, g1 + l * Ww, b1 + l * Ww, pyhi, pylo);
        // qkv = y @ Wqkv + bqkv  -> bf16 hi/lo
        gemm_tc<0,0,1><<<dim3(3 * Ww / 128, ROWS / 128), 256, GEMM_SMEM>>>(
            pyhi, pylo, wq_hi + oq, wq_lo + oq, bq, nullptr,
            nullptr, pqhi, pqlo, ROWS, Ww, 3 * Ww);
        // tensor-core attention -> bf16 hi/lo
        attn_tc<<<Bb * Hh * (Nn / 128), 256, ATTN_SMEM>>>(pqhi, pqlo, pahi, palo);
        // h = h + attn @ Wo + bo
        gemm_tc<1,0,0><<<dim3(Ww / 128, ROWS / 128), 256, GEMM_SMEM>>>(
            pahi, palo, wo_hi + oo, wo_lo + oo, bo_, h,
            h, nullptr, nullptr, ROWS, Ww, Ww);
        ln_kernel<<<ROWS, 256>>>(h, g2 + l * Ww, b2 + l * Ww, pyhi, pylo);
        // fc = gelu(y @ Wfc + bfc) -> bf16 hi/lo
        gemm_tc<0,1,1><<<dim3(4 * Ww / 128, ROWS / 128), 256, GEMM_SMEM>>>(
            pyhi, pylo, wf_hi + of, wf_lo + of, bf, nullptr,
            nullptr, pfchi, pfclo, ROWS, Ww, 4 * Ww);
        // h = h + fc @ Wpr + bpr
        gemm_tc<1,0,0><<<dim3(Ww / 128, ROWS / 128), 256, GEMM_SMEM>>>(
            pfchi, pfclo, wp_hi + op, wp_lo + op, bp, h,
            h, nullptr, nullptr, ROWS, 4 * Ww, Ww);
    }
}

// round 6
// speedup vs baseline: 3.6155x; 1.1659x over previous
#include <cuda_runtime.h>
#include <cuda_bf16.h>
#include <math.h>
#include <stdint.h>

// Problem constants
#define Lnum 8
#define Bb   8
#define Nn   1024
#define Ww   768
#define Hh   12
#define Cc   64
#define ROWS (Bb*Nn)          // 8192 token rows

// ---------------- scratch (no cudaMalloc allowed) ----------------
__device__ __nv_bfloat16 g_qkvhi[ROWS * 3 * Ww], g_qkvlo[ROWS * 3 * Ww];
__device__ __nv_bfloat16 g_yhi[ROWS * Ww],  g_ylo[ROWS * Ww];
__device__ __nv_bfloat16 g_ahi[ROWS * Ww],  g_alo[ROWS * Ww];
__device__ __nv_bfloat16 g_fchi[ROWS * 4 * Ww], g_fclo[ROWS * 4 * Ww];
__device__ __nv_bfloat16 g_wqkv_hi[Lnum * Ww * 3 * Ww], g_wqkv_lo[Lnum * Ww * 3 * Ww];
__device__ __nv_bfloat16 g_wo_hi  [Lnum * Ww * Ww],     g_wo_lo  [Lnum * Ww * Ww];
__device__ __nv_bfloat16 g_wfc_hi [Lnum * Ww * 4 * Ww], g_wfc_lo [Lnum * Ww * 4 * Ww];
__device__ __nv_bfloat16 g_wpr_hi [Lnum * 4 * Ww * Ww], g_wpr_lo [Lnum * 4 * Ww * Ww];

// =================== portable PTX helpers ===================
__device__ __forceinline__ uint32_t smem_to_u32(const void* smem_ptr) {
    uint32_t addr;
    asm("{ .reg .u64 tmp; cvta.to.shared.u64 tmp, %1; cvt.u32.u64 %0, tmp; }"
        : "=r"(addr) : "l"(smem_ptr));
    return addr;
}
__device__ __forceinline__ void ldsm_x4(uint32_t* r, uint32_t addr) {
    asm volatile("ldmatrix.sync.aligned.m8n8.x4.shared.b16 {%0,%1,%2,%3}, [%4];"
        : "=r"(r[0]), "=r"(r[1]), "=r"(r[2]), "=r"(r[3]) : "r"(addr));
}
__device__ __forceinline__ void ldsm_x2_t(uint32_t* r, uint32_t addr) {
    asm volatile("ldmatrix.sync.aligned.m8n8.x2.trans.shared.b16 {%0,%1}, [%2];"
        : "=r"(r[0]), "=r"(r[1]) : "r"(addr));
}
__device__ __forceinline__ void mma16816(float* d, const uint32_t* a, const uint32_t* b) {
    asm volatile(
        "mma.sync.aligned.m16n8k16.row.col.f32.bf16.bf16.f32 "
        "{%0,%1,%2,%3}, {%4,%5,%6,%7}, {%8,%9}, {%0,%1,%2,%3};\n"
        : "+f"(d[0]), "+f"(d[1]), "+f"(d[2]), "+f"(d[3])
        : "r"(a[0]), "r"(a[1]), "r"(a[2]), "r"(a[3]), "r"(b[0]), "r"(b[1]));
}
__device__ __forceinline__ void cp16(uint32_t s, const void* g) {
    asm volatile("cp.async.ca.shared.global [%0], [%1], 16;" :: "r"(s), "l"(g));
}
#define CP_COMMIT() asm volatile("cp.async.commit_group;")
#define CP_WAIT1()  asm volatile("cp.async.wait_group 1;")
#define CP_WAIT0()  asm volatile("cp.async.wait_group 0;")

__device__ __forceinline__ uint32_t bfpack(__nv_bfloat16 a, __nv_bfloat16 b) {
    uint16_t ua = *(uint16_t*)&a, ub = *(uint16_t*)&b;
    return (uint32_t)ua | ((uint32_t)ub << 16);
}
__device__ __forceinline__ void split2(float x, __nv_bfloat16& h, __nv_bfloat16& l) {
    h = __float2bfloat16(x);
    l = __float2bfloat16(x - __bfloat162float(h));
}

// ---------------- weight conversion ----------------
__global__ void __launch_bounds__(256) cvt_kernel(const float4* __restrict__ src,
                                                  uint2* __restrict__ hi,
                                                  uint2* __restrict__ lo,
                                                  int n4)
{
    int i = blockIdx.x * 256 + threadIdx.x;
    if (i >= n4) return;
    const float4 x = src[i];
    __nv_bfloat16 h0, h1, h2, h3, l0, l1, l2, l3;
    split2(x.x, h0, l0); split2(x.y, h1, l1);
    split2(x.z, h2, l2); split2(x.w, h3, l3);
    hi[i] = make_uint2(bfpack(h0, h1), bfpack(h2, h3));
    lo[i] = make_uint2(bfpack(l0, l1), bfpack(l2, l3));
}

// ---------------- LayerNorm: warp per row ----------------
__global__ void __launch_bounds__(256) ln_kernel(const float* __restrict__ x,
                                                 const float* __restrict__ g,
                                                 const float* __restrict__ b,
                                                 __nv_bfloat16* __restrict__ yhi,
                                                 __nv_bfloat16* __restrict__ ylo)
{
    const int warp = threadIdx.x >> 5;
    const int lane = threadIdx.x & 31;
    const int r = blockIdx.x * 8 + warp;
    const float* xr = x + (size_t)r * Ww;

    float4 v[6];
    float s = 0.f;
    #pragma unroll
    for (int i = 0; i < 6; i++) {
        v[i] = *(const float4*)(xr + (i * 32 + lane) * 4);
        s += v[i].x + v[i].y + v[i].z + v[i].w;
    }
    #pragma unroll
    for (int o = 16; o > 0; o >>= 1) s += __shfl_xor_sync(0xffffffffu, s, o);
    const float mean = s * (1.f / Ww);

    float s2 = 0.f;
    #pragma unroll
    for (int i = 0; i < 6; i++) {
        const float d0 = v[i].x - mean, d1 = v[i].y - mean;
        const float d2 = v[i].z - mean, d3 = v[i].w - mean;
        s2 += d0 * d0 + d1 * d1 + d2 * d2 + d3 * d3;
    }
    #pragma unroll
    for (int o = 16; o > 0; o >>= 1) s2 += __shfl_xor_sync(0xffffffffu, s2, o);
    const float w = rsqrtf(s2 * (1.f / Ww) + 1e-5f);

    #pragma unroll
    for (int i = 0; i < 6; i++) {
        const int c = (i * 32 + lane) * 4;
        const float4 gv = *(const float4*)(g + c);
        const float4 bv = *(const float4*)(b + c);
        float o0 = (v[i].x - mean) * w * gv.x + bv.x;
        float o1 = (v[i].y - mean) * w * gv.y + bv.y;
        float o2 = (v[i].z - mean) * w * gv.z + bv.z;
        float o3 = (v[i].w - mean) * w * gv.w + bv.w;
        __nv_bfloat16 h0, l0, h1, l1, h2, l2, h3, l3;
        split2(o0, h0, l0); split2(o1, h1, l1);
        split2(o2, h2, l2); split2(o3, h3, l3);
        *(uint2*)(yhi + (size_t)r * Ww + c) = make_uint2(bfpack(h0, h1), bfpack(h2, h3));
        *(uint2*)(ylo + (size_t)r * Ww + c) = make_uint2(bfpack(l0, l1), bfpack(l2, l3));
    }
}

// =================== bf16x3 tensor-core GEMM, cp.async fill, 2 CTAs/SM ===========
#define A_STRB 80
#define B_STRB 272
#define A_BYTES (128 * A_STRB)
#define B_BYTES (32 * B_STRB)
#define OFF_ALO A_BYTES
#define OFF_BHI (2*A_BYTES)
#define OFF_BLO (2*A_BYTES + B_BYTES)
#define BUF_BYTES (2*A_BYTES + 2*B_BYTES)
#define GEMM_SMEM (2 * BUF_BYTES)

template<int RES, int GELU, int OUTBF>
__global__ void __launch_bounds__(256, 2) gemm_tc(const __nv_bfloat16* __restrict__ Ahi,
                                                  const __nv_bfloat16* __restrict__ Alo,
                                                  const __nv_bfloat16* __restrict__ Bhi,
                                                  const __nv_bfloat16* __restrict__ Blo,
                                                  const float* __restrict__ bias,
                                                  const float* __restrict__ Rz,
                                                  float* __restrict__ C,
                                                  __nv_bfloat16* __restrict__ Chi,
                                                  __nv_bfloat16* __restrict__ Clo,
                                                  int M, int K, int N)
{
    extern __shared__ char sm[];
    const uint32_t smem_base = smem_to_u32(sm);
    const int tid  = threadIdx.x;
    const int wid  = tid >> 5;
    const int lane = tid & 31;
    const int wm   = wid >> 2;
    const int wn   = wid & 3;
    const int n0 = blockIdx.x * 128;
    const int m0 = blockIdx.y * 128;

    float acc[4][4][4];
    #pragma unroll
    for (int i = 0; i < 4; i++)
        #pragma unroll
        for (int j = 0; j < 4; j++)
            #pragma unroll
            for (int q = 0; q < 4; q++) acc[i][j][q] = 0.f;

    const int NC = K / 32;

    const int a_r = tid >> 1;
    const int a_p = (tid & 1) * 2;
    const int b_r = tid >> 3;
    const int b_p = (tid & 7) * 2;

    auto issue_chunk = [&](int kc, int bsel) {
        const uint32_t buf = smem_base + bsel * BUF_BYTES;
        const uint32_t aoff = (uint32_t)a_r * A_STRB + a_p * 16;
        const __nv_bfloat16* ah = Ahi + (size_t)(m0 + a_r) * K + kc * 32 + a_p * 8;
        const __nv_bfloat16* al = Alo + (size_t)(m0 + a_r) * K + kc * 32 + a_p * 8;
        cp16(buf + aoff,                ah);
        cp16(buf + aoff + 16,           ah + 8);
        cp16(buf + OFF_ALO + aoff,      al);
        cp16(buf + OFF_ALO + aoff + 16, al + 8);
        const uint32_t boff = (uint32_t)b_r * B_STRB + b_p * 16;
        const __nv_bfloat16* bh = Bhi + (size_t)(kc * 32 + b_r) * N + n0 + b_p * 8;
        const __nv_bfloat16* bl = Blo + (size_t)(kc * 32 + b_r) * N + n0 + b_p * 8;
        cp16(buf + OFF_BHI + boff,      bh);
        cp16(buf + OFF_BHI + boff + 16, bh + 8);
        cp16(buf + OFF_BLO + boff,      bl);
        cp16(buf + OFF_BLO + boff + 16, bl + 8);
    };

    const uint32_t a_lrow = (uint32_t)(wm * 64 + (lane & 15));
    const uint32_t a_koff = (uint32_t)(8 * (lane >> 4));
    const uint32_t b_lrow = (uint32_t)(lane & 15);
    const uint32_t b_noff = (uint32_t)(wn * 32);

    issue_chunk(0, 0); CP_COMMIT();
    issue_chunk(1, 1); CP_COMMIT();

    for (int ic = 0; ic < NC; ic++) {
        CP_WAIT1();
        __syncthreads();

        const uint32_t buf = smem_base + (ic & 1) * BUF_BYTES;
        #pragma unroll
        for (int k16 = 0; k16 < 2; k16++) {
            uint32_t ah[4][4], al[4][4];
            #pragma unroll
            for (int mi = 0; mi < 4; mi++) {
                const uint32_t aoff = (a_lrow + mi * 16) * A_STRB
                                    + (k16 * 16 + a_koff) * 2;
                ldsm_x4(ah[mi], buf + aoff);
                ldsm_x4(al[mi], buf + OFF_ALO + aoff);
            }
            #pragma unroll
            for (int ni = 0; ni < 4; ni++) {
                uint32_t bh[2], bl[2];
                const uint32_t boff = (k16 * 16 + b_lrow) * B_STRB
                                    + (b_noff + ni * 8) * 2;
                ldsm_x2_t(bh, buf + OFF_BHI + boff);
                ldsm_x2_t(bl, buf + OFF_BLO + boff);
                #pragma unroll
                for (int mi = 0; mi < 4; mi++) {
                    mma16816(acc[mi][ni], ah[mi], bh);
                    mma16816(acc[mi][ni], ah[mi], bl);
                    mma16816(acc[mi][ni], al[mi], bh);
                }
            }
        }

        __syncthreads();
        if (ic + 2 < NC) issue_chunk(ic + 2, ic & 1);
        CP_COMMIT();
    }

    const int g = lane >> 2;
    const int t = lane & 3;
    #pragma unroll
    for (int mi = 0; mi < 4; mi++) {
        #pragma unroll
        for (int half = 0; half < 2; half++) {
            const int m_ = m0 + wm * 64 + mi * 16 + g + half * 8;
            #pragma unroll
            for (int ni = 0; ni < 4; ni++) {
                const int n_ = n0 + wn * 32 + ni * 8 + 2 * t;
                float v0 = acc[mi][ni][half * 2 + 0] + bias[n_];
                float v1 = acc[mi][ni][half * 2 + 1] + bias[n_ + 1];
                if (GELU) {
                    v0 = 0.5f * v0 * (1.0f + erff(v0 * 0.70710678118654752f));
                    v1 = 0.5f * v1 * (1.0f + erff(v1 * 0.70710678118654752f));
                }
                if (RES) {
                    const float2 rv = *(const float2*)(Rz + (size_t)m_ * N + n_);
                    v0 += rv.x; v1 += rv.y;
                }
                if (OUTBF) {
                    __nv_bfloat16 h0, l0, h1, l1;
                    split2(v0, h0, l0); split2(v1, h1, l1);
                    *(uint32_t*)(Chi + (size_t)m_ * N + n_) = bfpack(h0, h1);
                    *(uint32_t*)(Clo + (size_t)m_ * N + n_) = bfpack(l0, l1);
                } else {
                    *(float2*)(C + (size_t)m_ * N + n_) = make_float2(v0, v1);
                }
            }
        }
    }
}

// =================== tensor-core flash attention (bf16x3) — unchanged ===================
#define AT_STR 144
#define AT_OFF_QLO (128*AT_STR)
#define AT_OFF_KV  (2*128*AT_STR)
#define AT_BUF     (4*64*AT_STR)
#define AT_KHI 0
#define AT_KLO (64*AT_STR)
#define AT_VHI (2*64*AT_STR)
#define AT_VLO (3*64*AT_STR)
#define ATTN_SMEM (AT_OFF_KV + 2*AT_BUF)

__global__ void __launch_bounds__(256) attn_tc(const __nv_bfloat16* __restrict__ qhi,
                                               const __nv_bfloat16* __restrict__ qlo,
                                               __nv_bfloat16* __restrict__ ohi,
                                               __nv_bfloat16* __restrict__ olo)
{
    extern __shared__ char sm[];
    const uint32_t sb = smem_to_u32(sm);
    const int tid  = threadIdx.x;
    const int warp = tid >> 5;
    const int lane = tid & 31;
    const int g    = lane >> 2;
    const int t    = lane & 3;
    const int blk  = blockIdx.x;
    const int bh   = blk >> 3;
    const int rb   = blk & 7;
    const int b    = bh / Hh;
    const int h    = bh % Hh;
    const int rowbase = b * Nn + rb * 128;
    const int colq = h * 3 * Cc;

    #pragma unroll
    for (int i = 0; i < 4; i++) {
        const int flat = tid + i * 256;
        const int row = flat >> 3, c8 = flat & 7;
        const size_t goff = (size_t)(rowbase + row) * (3 * Ww) + colq + c8 * 8;
        cp16(sb + row * AT_STR + c8 * 16, qhi + goff);
        cp16(sb + AT_OFF_QLO + row * AT_STR + c8 * 16, qlo + goff);
    }
    auto issue_kv = [&](int kt, int bsel) {
        const uint32_t kvb = sb + AT_OFF_KV + bsel * AT_BUF;
        #pragma unroll
        for (int i = 0; i < 2; i++) {
            const int flat = tid + i * 256;
            const int row = flat >> 3, c8 = flat & 7;
            const size_t go = (size_t)(b * Nn + kt * 64 + row) * (3 * Ww) + colq + c8 * 8;
            const uint32_t so = row * AT_STR + c8 * 16;
            cp16(kvb + AT_KHI + so, qhi + go + 64);
            cp16(kvb + AT_KLO + so, qlo + go + 64);
            cp16(kvb + AT_VHI + so, qhi + go + 128);
            cp16(kvb + AT_VLO + so, qlo + go + 128);
        }
    };
    issue_kv(0, 0);
    CP_COMMIT();

    float m0r = -1e30f, m1r = -1e30f, l0r = 0.f, l1r = 0.f;
    float O[8][4];
    #pragma unroll
    for (int j = 0; j < 8; j++)
        #pragma unroll
        for (int q = 0; q < 4; q++) O[j][q] = 0.f;

    const uint32_t q_lrow = (uint32_t)(16 * warp + (lane & 15));
    const uint32_t q_koff = (uint32_t)(8 * (lane >> 4));
    const int k_nrow = (lane & 7) + ((lane >> 4) << 3);
    const int k_koff = ((lane >> 3) & 1) * 8;
    const int v_krow = lane & 15;

    for (int kt = 0; kt < 16; kt++) {
        if (kt + 1 < 16) { issue_kv(kt + 1, (kt + 1) & 1); CP_COMMIT(); CP_WAIT1(); }
        else CP_WAIT0();
        __syncthreads();

        const uint32_t kvb = sb + AT_OFF_KV + (kt & 1) * AT_BUF;

        float s[8][4];
        #pragma unroll
        for (int j = 0; j < 8; j++)
            #pragma unroll
            for (int q = 0; q < 4; q++) s[j][q] = 0.f;

        #pragma unroll
        for (int k16 = 0; k16 < 4; k16++) {
            uint32_t ah[4], al[4];
            const uint32_t qo = q_lrow * AT_STR + (k16 * 16 + q_koff) * 2;
            ldsm_x4(ah, sb + qo);
            ldsm_x4(al, sb + AT_OFF_QLO + qo);
            #pragma unroll
            for (int jj = 0; jj < 4; jj++) {
                uint32_t kh[4], kl[4];
                const uint32_t ko = (uint32_t)(16 * jj + k_nrow) * AT_STR
                                  + (k16 * 16 + k_koff) * 2;
                ldsm_x4(kh, kvb + AT_KHI + ko);
                ldsm_x4(kl, kvb + AT_KLO + ko);
                mma16816(s[2*jj],   ah, &kh[0]);
                mma16816(s[2*jj],   ah, &kl[0]);
                mma16816(s[2*jj],   al, &kh[0]);
                mma16816(s[2*jj+1], ah, &kh[2]);
                mma16816(s[2*jj+1], ah, &kl[2]);
                mma16816(s[2*jj+1], al, &kh[2]);
            }
        }

        float mx0 = -1e30f, mx1 = -1e30f;
        #pragma unroll
        for (int j = 0; j < 8; j++) {
            s[j][0] *= 0.125f; s[j][1] *= 0.125f; s[j][2] *= 0.125f; s[j][3] *= 0.125f;
            mx0 = fmaxf(mx0, fmaxf(s[j][0], s[j][1]));
            mx1 = fmaxf(mx1, fmaxf(s[j][2], s[j][3]));
        }
        mx0 = fmaxf(mx0, __shfl_xor_sync(0xffffffffu, mx0, 1));
        mx0 = fmaxf(mx0, __shfl_xor_sync(0xffffffffu, mx0, 2));
        mx1 = fmaxf(mx1, __shfl_xor_sync(0xffffffffu, mx1, 1));
        mx1 = fmaxf(mx1, __shfl_xor_sync(0xffffffffu, mx1, 2));
        const float mn0 = fmaxf(m0r, mx0);
        const float mn1 = fmaxf(m1r, mx1);
        const float al0 = __expf(m0r - mn0);
        const float al1 = __expf(m1r - mn1);
        m0r = mn0; m1r = mn1;
        float ps0 = 0.f, ps1 = 0.f;
        #pragma unroll
        for (int j = 0; j < 8; j++) {
            s[j][0] = __expf(s[j][0] - mn0);
            s[j][1] = __expf(s[j][1] - mn0);
            s[j][2] = __expf(s[j][2] - mn1);
            s[j][3] = __expf(s[j][3] - mn1);
            ps0 += s[j][0] + s[j][1];
            ps1 += s[j][2] + s[j][3];
        }
        l0r = l0r * al0 + ps0;
        l1r = l1r * al1 + ps1;
        #pragma unroll
        for (int j = 0; j < 8; j++) {
            O[j][0] *= al0; O[j][1] *= al0; O[j][2] *= al1; O[j][3] *= al1;
        }

        #pragma unroll
        for (int kk = 0; kk < 4; kk++) {
            uint32_t aph[4], apl[4];
            #pragma unroll
            for (int q2 = 0; q2 < 2; q2++) {
                #pragma unroll
                for (int jj = 0; jj < 2; jj++) {
                    const int j = 2 * kk + jj;
                    __nv_bfloat16 h0, l0, h1, l1;
                    split2(s[j][2*q2 + 0], h0, l0);
                    split2(s[j][2*q2 + 1], h1, l1);
                    aph[jj * 2 + q2] = bfpack(h0, h1);
                    apl[jj * 2 + q2] = bfpack(l0, l1);
                }
            }
            #pragma unroll
            for (int j = 0; j < 8; j++) {
                uint32_t vh[2], vl[2];
                const uint32_t vo = (uint32_t)(kk * 16 + v_krow) * AT_STR + (8 * j) * 2;
                ldsm_x2_t(vh, kvb + AT_VHI + vo);
                ldsm_x2_t(vl, kvb + AT_VLO + vo);
                mma16816(O[j], aph, vh);
                mma16816(O[j], aph, vl);
                mma16816(O[j], apl, vh);
            }
        }
        __syncthreads();
    }

    l0r += __shfl_xor_sync(0xffffffffu, l0r, 1);
    l0r += __shfl_xor_sync(0xffffffffu, l0r, 2);
    l1r += __shfl_xor_sync(0xffffffffu, l1r, 1);
    l1r += __shfl_xor_sync(0xffffffffu, l1r, 2);
    const float inv0 = 1.f / l0r;
    const float inv1 = 1.f / l1r;
    const int row0 = rowbase + 16 * warp + g;
    const int row1 = row0 + 8;
    #pragma unroll
    for (int j = 0; j < 8; j++) {
        const int col = h * Cc + 8 * j + 2 * t;
        float v0 = O[j][0] * inv0, v1 = O[j][1] * inv0;
        float w0 = O[j][2] * inv1, w1 = O[j][3] * inv1;
        __nv_bfloat16 h0, l0, h1, l1;
        split2(v0, h0, l0); split2(v1, h1, l1);
        *(uint32_t*)(ohi + (size_t)row0 * Ww + col) = bfpack(h0, h1);
        *(uint32_t*)(olo + (size_t)row0 * Ww + col) = bfpack(l0, l1);
        split2(w0, h0, l0); split2(w1, h1, l1);
        *(uint32_t*)(ohi + (size_t)row1 * Ww + col) = bfpack(h0, h1);
        *(uint32_t*)(olo + (size_t)row1 * Ww + col) = bfpack(l0, l1);
    }
}

// ---------------- launcher ----------------
extern "C" void kernel_launch(void* const* d_in, const int* in_sizes, int n_in,
                              void* d_out, int out_size)
{
    const float* x    = (const float*)d_in[0];
    const float* Wqkv = (const float*)d_in[1];
    const float* bqkv = (const float*)d_in[2];
    const float* Wo   = (const float*)d_in[3];
    const float* bo   = (const float*)d_in[4];
    const float* Wfc  = (const float*)d_in[5];
    const float* bfc  = (const float*)d_in[6];
    const float* Wpr  = (const float*)d_in[7];
    const float* bpr  = (const float*)d_in[8];
    const float* g1   = (const float*)d_in[9];
    const float* b1   = (const float*)d_in[10];
    const float* g2   = (const float*)d_in[11];
    const float* b2   = (const float*)d_in[12];

    float* h = (float*)d_out;

    __nv_bfloat16 *pqhi, *pqlo, *pyhi, *pylo, *pahi, *palo, *pfchi, *pfclo;
    __nv_bfloat16 *wq_hi, *wq_lo, *wo_hi, *wo_lo, *wf_hi, *wf_lo, *wp_hi, *wp_lo;
    cudaGetSymbolAddress((void**)&pqhi,  g_qkvhi);
    cudaGetSymbolAddress((void**)&pqlo,  g_qkvlo);
    cudaGetSymbolAddress((void**)&pyhi,  g_yhi);
    cudaGetSymbolAddress((void**)&pylo,  g_ylo);
    cudaGetSymbolAddress((void**)&pahi,  g_ahi);
    cudaGetSymbolAddress((void**)&palo,  g_alo);
    cudaGetSymbolAddress((void**)&pfchi, g_fchi);
    cudaGetSymbolAddress((void**)&pfclo, g_fclo);
    cudaGetSymbolAddress((void**)&wq_hi, g_wqkv_hi);
    cudaGetSymbolAddress((void**)&wq_lo, g_wqkv_lo);
    cudaGetSymbolAddress((void**)&wo_hi, g_wo_hi);
    cudaGetSymbolAddress((void**)&wo_lo, g_wo_lo);
    cudaGetSymbolAddress((void**)&wf_hi, g_wfc_hi);
    cudaGetSymbolAddress((void**)&wf_lo, g_wfc_lo);
    cudaGetSymbolAddress((void**)&wp_hi, g_wpr_hi);
    cudaGetSymbolAddress((void**)&wp_lo, g_wpr_lo);

    cudaFuncSetAttribute(gemm_tc<0,0,1>, cudaFuncAttributeMaxDynamicSharedMemorySize, GEMM_SMEM);
    cudaFuncSetAttribute(gemm_tc<1,0,0>, cudaFuncAttributeMaxDynamicSharedMemorySize, GEMM_SMEM);
    cudaFuncSetAttribute(gemm_tc<0,1,1>, cudaFuncAttributeMaxDynamicSharedMemorySize, GEMM_SMEM);
    cudaFuncSetAttribute(attn_tc,        cudaFuncAttributeMaxDynamicSharedMemorySize, ATTN_SMEM);

    cudaMemcpyAsync(h, x, (size_t)ROWS * Ww * sizeof(float), cudaMemcpyDeviceToDevice);

    {
        int n4;
        n4 = Lnum * Ww * 3 * Ww / 4;
        cvt_kernel<<<(n4 + 255) / 256, 256>>>((const float4*)Wqkv, (uint2*)wq_hi, (uint2*)wq_lo, n4);
        n4 = Lnum * Ww * Ww / 4;
        cvt_kernel<<<(n4 + 255) / 256, 256>>>((const float4*)Wo,   (uint2*)wo_hi, (uint2*)wo_lo, n4);
        n4 = Lnum * Ww * 4 * Ww / 4;
        cvt_kernel<<<(n4 + 255) / 256, 256>>>((const float4*)Wfc,  (uint2*)wf_hi, (uint2*)wf_lo, n4);
        n4 = Lnum * 4 * Ww * Ww / 4;
        cvt_kernel<<<(n4 + 255) / 256, 256>>>((const float4*)Wpr,  (uint2*)wp_hi, (uint2*)wp_lo, n4);
    }

    for (int l = 0; l < Lnum; l++) {
        const size_t oq = (size_t)l * Ww * 3 * Ww;
        const size_t oo = (size_t)l * Ww * Ww;
        const size_t of = (size_t)l * Ww * 4 * Ww;
        const size_t op = (size_t)l * 4 * Ww * Ww;
        const float* bq  = bqkv + (size_t)l * 3 * Ww;
        const float* bo_ = bo   + (size_t)l * Ww;
        const float* bf  = bfc  + (size_t)l * 4 * Ww;
        const float* bp  = bpr  + (size_t)l * Ww;

        ln_kernel<<<ROWS / 8, 256>>>(h, g1 + l * Ww, b1 + l * Ww, pyhi, pylo);
        gemm_tc<0,0,1><<<dim3(3 * Ww / 128, ROWS / 128), 256, GEMM_SMEM>>>(
            pyhi, pylo, wq_hi + oq, wq_lo + oq, bq, nullptr,
            nullptr, pqhi, pqlo, ROWS, Ww, 3 * Ww);
        attn_tc<<<Bb * Hh * (Nn / 128), 256, ATTN_SMEM>>>(pqhi, pqlo, pahi, palo);
        gemm_tc<1,0,0><<<dim3(Ww / 128, ROWS / 128), 256, GEMM_SMEM>>>(
            pahi, palo, wo_hi + oo, wo_lo + oo, bo_, h,
            h, nullptr, nullptr, ROWS, Ww, Ww);
        ln_kernel<<<ROWS / 8, 256>>>(h, g2 + l * Ww, b2 + l * Ww, pyhi, pylo);
        gemm_tc<0,1,1><<<dim3(4 * Ww / 128, ROWS / 128), 256, GEMM_SMEM>>>(
            pyhi, pylo, wf_hi + of, wf_lo + of, bf, nullptr,
            nullptr, pfchi, pfclo, ROWS, Ww, 4 * Ww);
        gemm_tc<1,0,0><<<dim3(Ww / 128, ROWS / 128), 256, GEMM_SMEM>>>(
            pfchi, pfclo, wp_hi + op, wp_lo + op, bp, h,
            h, nullptr, nullptr, ROWS, 4 * Ww, Ww);
    }
}